// round 13
// baseline (speedup 1.0000x reference)
#include <cuda_runtime.h>
#include <cuda_bf16.h>
#include <math.h>
#include <stdint.h>

#define BB 16
#define LL 128
#define HH 20
#define GG 80
#define MR (BB*LL)
#define KSPL 37
#define KP1 27808
#define S3OFF1 896
#define KP2 8432
#define S3OFF2 432

__device__ __align__(256) float g_a[MR*32];
__device__ __align__(256) float g_X1[(size_t)MR*KP1];
__device__ __align__(256) float g_X2[(size_t)MR*KP2];
__device__ __align__(256) float2 g_sp[(size_t)BB*KP1];
__device__ float g_mean[KP1];
__device__ __align__(256) unsigned short g_Wh[(size_t)GG*KP1];
__device__ __align__(256) unsigned short g_Wl[(size_t)GG*KP1];
__device__ float g_pb[GG];
__device__ float g_xproj[MR*GG];
__device__ float g_part[(size_t)KSPL*MR*GG];
__device__ float g_o[MR*HH];

__device__ __forceinline__ uint32_t bf2pack(float lo_elem, float hi_elem) {
    uint32_t w;
    asm("cvt.rn.bf16x2.f32 %0, %1, %2;" : "=r"(w) : "f"(hi_elem), "f"(lo_elem));
    return w;
}
__device__ __forceinline__ void split_pair(float vx, float vy, uint32_t& wh, uint32_t& wl) {
    wh = bf2pack(vx, vy);
    float hx = __uint_as_float(wh << 16);
    float hy = __uint_as_float(wh & 0xFFFF0000u);
    wl = bf2pack(vx - hx, vy - hy);
}
__device__ __forceinline__ void mma_bf16(float* c, const uint32_t* a, const uint32_t* b) {
    asm("mma.sync.aligned.m16n8k16.row.col.f32.bf16.bf16.f32 "
        "{%0,%1,%2,%3}, {%4,%5,%6,%7}, {%8,%9}, {%0,%1,%2,%3};"
        : "+f"(c[0]), "+f"(c[1]), "+f"(c[2]), "+f"(c[3])
        : "r"(a[0]), "r"(a[1]), "r"(a[2]), "r"(a[3]), "r"(b[0]), "r"(b[1]));
}
__device__ __forceinline__ float tanh_ap(float x) {
    float y; asm("tanh.approx.f32 %0, %1;" : "=f"(y) : "f"(x)); return y;
}
__device__ __forceinline__ float sigf(float x) { return fmaf(0.5f, tanh_ap(0.5f*x), 0.5f); }

__global__ void augment_kernel(const float* __restrict__ inp,
                               const float* __restrict__ w1, const float* __restrict__ b1,
                               const float* __restrict__ w2, const float* __restrict__ b2) {
    int bl = blockIdx.x;
    int l = bl & (LL-1);
    int tid = threadIdx.x; // 64
    __shared__ float xin[20], hid[64], out8[8];
    if (tid < 20) xin[tid] = inp[bl*20 + tid];
    __syncthreads();
    {
        float a = b1[tid];
        const float* wr = w1 + tid*20;
        #pragma unroll
        for (int c = 0; c < 20; c++) a = fmaf(wr[c], xin[c], a);
        hid[tid] = fmaxf(a, 0.f);
    }
    __syncthreads();
    if (tid < 8) {
        float a = b2[tid];
        const float* wr = w2 + tid*64;
        #pragma unroll 8
        for (int c = 0; c < 64; c++) a = fmaf(wr[c], hid[c], a);
        out8[tid] = a;
    }
    __syncthreads();
    if (tid < 32) {
        float v = 0.f;
        if (tid == 0) v = (float)l * (1.0f/127.0f);
        else if (tid < 21) v = xin[tid-1];
        else if (tid < 29) v = out8[tid-21];
        g_a[bl*32 + tid] = v;
    }
}

// streamed depth-3 signature with fused BN-stat partials
template<int C, int RUN, int S3OFF, int KP, int NSPLIT>
__global__ void sig_kernel(const float* __restrict__ in, int instride,
                           float* __restrict__ X) {
    int g = blockIdx.x, b = blockIdx.y;
    int i0 = (g*C)/NSPLIT, i1 = ((g+1)*C)/NSPLIT;
    int tid = threadIdx.x;
    __shared__ __align__(16) float d[32];
    __shared__ float s1[32];
    int np = (i1 - i0) * C;
    bool act = tid < np;
    int i = i0 + tid / C, j = tid % C;
    int pg = i*C + j;
    float s2r = 0.f, sms2 = 0.f, sqs2 = 0.f;
    float s3r[RUN], sm3[RUN], sq3[RUN];
    #pragma unroll
    for (int q = 0; q < RUN; q++) { s3r[q] = 0.f; sm3[q] = 0.f; sq3[q] = 0.f; }
    float s1sum = 0.f, s1sq = 0.f;
    float prev = 0.f;
    if (tid < 32) { d[tid] = 0.f; s1[tid] = 0.f; }
    float nxt = (tid < C) ? in[(b*LL)*instride + tid] : 0.f;
    __syncthreads();
    for (int t = 0; t < LL; t++) {
        if (tid < 32) {
            float cur = (tid < C) ? nxt : 0.f;
            d[tid] = cur - prev;
            prev = cur;
        }
        __syncthreads();
        if (tid < C && t+1 < LL) nxt = in[(b*LL + t+1)*instride + tid];
        float* Xr = X + (size_t)(b*LL + t)*KP;
        if (act) {
            float di = d[i], dj = d[j], s1i = s1[i];
            float gam = fmaf(dj, fmaf(di, (1.f/6.f), 0.5f*s1i), s2r);
            s2r = fmaf(dj, fmaf(0.5f, di, s1i), s2r);
            sms2 += s2r; sqs2 = fmaf(s2r, s2r, sqs2);
            const float4* d4 = (const float4*)d;
            float4* o4 = (float4*)(Xr + S3OFF + pg*RUN);
            #pragma unroll
            for (int q = 0; q < RUN/4; q++) {
                float4 dq = d4[q];
                s3r[4*q+0] = fmaf(gam, dq.x, s3r[4*q+0]);
                s3r[4*q+1] = fmaf(gam, dq.y, s3r[4*q+1]);
                s3r[4*q+2] = fmaf(gam, dq.z, s3r[4*q+2]);
                s3r[4*q+3] = fmaf(gam, dq.w, s3r[4*q+3]);
                o4[q] = make_float4(s3r[4*q+0], s3r[4*q+1], s3r[4*q+2], s3r[4*q+3]);
                sm3[4*q+0] += s3r[4*q+0]; sq3[4*q+0] = fmaf(s3r[4*q+0], s3r[4*q+0], sq3[4*q+0]);
                sm3[4*q+1] += s3r[4*q+1]; sq3[4*q+1] = fmaf(s3r[4*q+1], s3r[4*q+1], sq3[4*q+1]);
                sm3[4*q+2] += s3r[4*q+2]; sq3[4*q+2] = fmaf(s3r[4*q+2], s3r[4*q+2], sq3[4*q+2]);
                sm3[4*q+3] += s3r[4*q+3]; sq3[4*q+3] = fmaf(s3r[4*q+3], s3r[4*q+3], sq3[4*q+3]);
            }
            Xr[32 + pg] = s2r;
        }
        __syncthreads();
        if (tid < C) s1[tid] += d[tid];
        if (g == 0) {
            float v = 0.f;
            if (tid < C) v = s1[tid];
            if (tid < 32) {
                Xr[tid] = v;
                s1sum += v; s1sq = fmaf(v, v, s1sq);
            }
            int gap0 = 32 + C*C;
            if (gap0 + tid < S3OFF) Xr[gap0 + tid] = 0.f;
        }
    }
    float2* SP = g_sp + (size_t)b*KP;
    if (act) {
        SP[32 + pg] = make_float2(sms2, sqs2);
        #pragma unroll
        for (int q = 0; q < RUN; q++)
            SP[S3OFF + pg*RUN + q] = make_float2(sm3[q], sq3[q]);
    }
    if (g == 0 && tid < 32) {
        SP[tid] = make_float2(s1sum, s1sq);
        int gap0 = 32 + C*C;
        if (gap0 + tid < S3OFF) SP[gap0 + tid] = make_float2(0.f, 0.f);
    }
}

// merged per-channel stats + BN weight fold (block-cooperative, coalesced)
template<int C, int S3OFF, int RUN, int KP>
__global__ void statsfold_kernel(const float* __restrict__ W) {
    __shared__ float istd_s[128];
    int cp0 = blockIdx.x * 128;
    int tid = threadIdx.x;   // 256
    if (tid < 128) {
        int cp = cp0 + tid;
        float istd = 0.f;
        if (cp < KP) {
            double s = 0.0, q = 0.0;
            #pragma unroll
            for (int b = 0; b < BB; b++) {
                float2 v = g_sp[(size_t)b*KP + cp];
                s += (double)v.x; q += (double)v.y;
            }
            double m = s * (1.0/2048.0);
            double var = q * (1.0/2048.0) - m*m;
            istd = (float)(1.0 / sqrt(var + 1e-5));
            g_mean[cp] = (float)m;
        }
        istd_s[tid] = istd;
    }
    __syncthreads();
    const int CP = C*C;
    const int CW = C + CP + CP*C;
    for (int e = tid; e < GG*128; e += 256) {
        int g = e >> 7, ci = e & 127;
        int cp = cp0 + ci;
        if (cp >= KP) continue;
        int c = -1;
        if (cp < 32) { if (cp < C) c = cp; }
        else if (cp < 32 + CP) c = C + (cp - 32);
        else if (cp >= S3OFF) {
            int r = cp - S3OFF; int p = r / RUN; int k = r - p*RUN;
            if (k < C) c = C + CP + p*C + k;
        }
        float v = (c >= 0) ? W[(size_t)g*CW + c] * istd_s[ci] : 0.f;
        unsigned short hb;
        asm("cvt.rn.bf16.f32 %0, %1;" : "=h"(hb) : "f"(v));
        float hf = __uint_as_float(((uint32_t)hb) << 16);
        unsigned short lb;
        asm("cvt.rn.bf16.f32 %0, %1;" : "=h"(lb) : "f"(v - hf));
        g_Wh[(size_t)g*KP + cp] = hb;
        g_Wl[(size_t)g*KP + cp] = lb;
    }
}

__global__ void __launch_bounds__(1024) projbias_kernel(const float* __restrict__ bih,
                                                        const float* __restrict__ bhh, int KP) {
    int g = blockIdx.x, tid = threadIdx.x;
    __shared__ double red[1024];
    double s = 0.0;
    for (int c = tid; c < KP; c += 1024) {
        float w = __uint_as_float(((uint32_t)g_Wh[(size_t)g*KP + c]) << 16)
                + __uint_as_float(((uint32_t)g_Wl[(size_t)g*KP + c]) << 16);
        s += (double)w * (double)g_mean[c];
    }
    red[tid] = s; __syncthreads();
    for (int st = 512; st > 0; st >>= 1) { if (tid < st) red[tid] += red[tid+st]; __syncthreads(); }
    if (tid == 0) g_pb[g] = bih[g] + bhh[g] - (float)red[0];
}

// tensor-core GEMM: bf16 2-term split, 3 passes, m16n8k16, pipelined loads
__global__ void __launch_bounds__(256) gemm_tc(const float* __restrict__ X, int KP, int KC) {
    __shared__ __align__(16) uint32_t Ah[128*12];
    __shared__ __align__(16) uint32_t Al[128*12];
    __shared__ __align__(16) uint32_t Bh[80*12];
    __shared__ __align__(16) uint32_t Bl[80*12];
    int m0 = blockIdx.x * 128;
    int ks = blockIdx.y;
    int k0 = ks * KC;
    int kend = min(k0 + KC, KP);
    int tid = threadIdx.x;
    int warp = tid >> 5, lane = tid & 31;
    int wm = warp & 3, wn = warp >> 2;
    int gq = lane >> 2, tig = lane & 3;
    float acc[2][5][4];
    #pragma unroll
    for (int mi = 0; mi < 2; mi++)
        #pragma unroll
        for (int ni = 0; ni < 5; ni++)
            #pragma unroll
            for (int q = 0; q < 4; q++) acc[mi][ni][q] = 0.f;

    int arow0 = tid >> 2,        akq0 = (tid & 3) << 2;
    int arow1 = (tid+256) >> 2,  akq1 = akq0;
    int s0 = tid;
    int b0_lo = (s0 >= 160);  int b0r = (b0_lo ? s0-160 : s0) >> 1;  int b0s = s0 & 1;
    int s1v = tid + 256;      bool hasB1 = (s1v < 320);
    int b1r = (s1v-160) >> 1; int b1s = s1v & 1;

    if (k0 < kend) {
        float4 pa0, pa1; uint4 pb0, pb1;
        int kb = k0;
        pa0 = *(const float4*)(X + (size_t)(m0 + arow0)*KP + kb + akq0);
        pa1 = *(const float4*)(X + (size_t)(m0 + arow1)*KP + kb + akq1);
        {
            const unsigned short* bp0 = (b0_lo ? g_Wl : g_Wh) + (size_t)b0r*KP + kb + 8*b0s;
            pb0 = *(const uint4*)bp0;
            if (hasB1) pb1 = *(const uint4*)(g_Wl + (size_t)b1r*KP + kb + 8*b1s);
        }
        for (; kb < kend; kb += 16) {
            {
                uint32_t wh, wl, wh2, wl2;
                split_pair(pa0.x, pa0.y, wh, wl);
                split_pair(pa0.z, pa0.w, wh2, wl2);
                *(uint2*)(Ah + arow0*12 + (akq0>>1)) = make_uint2(wh, wh2);
                *(uint2*)(Al + arow0*12 + (akq0>>1)) = make_uint2(wl, wl2);
                split_pair(pa1.x, pa1.y, wh, wl);
                split_pair(pa1.z, pa1.w, wh2, wl2);
                *(uint2*)(Ah + arow1*12 + (akq1>>1)) = make_uint2(wh, wh2);
                *(uint2*)(Al + arow1*12 + (akq1>>1)) = make_uint2(wl, wl2);
            }
            {
                uint32_t* buf = b0_lo ? Bl : Bh;
                *(uint4*)(buf + b0r*12 + 4*b0s) = pb0;
                if (hasB1) *(uint4*)(Bl + b1r*12 + 4*b1s) = pb1;
            }
            __syncthreads();
            if (kb + 16 < kend) {
                int kn = kb + 16;
                pa0 = *(const float4*)(X + (size_t)(m0 + arow0)*KP + kn + akq0);
                pa1 = *(const float4*)(X + (size_t)(m0 + arow1)*KP + kn + akq1);
                const unsigned short* bp0 = (b0_lo ? g_Wl : g_Wh) + (size_t)b0r*KP + kn + 8*b0s;
                pb0 = *(const uint4*)bp0;
                if (hasB1) pb1 = *(const uint4*)(g_Wl + (size_t)b1r*KP + kn + 8*b1s);
            }
            uint32_t ah[2][4], al[2][4], bh[5][2], bl[5][2];
            #pragma unroll
            for (int mi = 0; mi < 2; mi++) {
                int rb = wm*32 + mi*16;
                ah[mi][0] = Ah[(rb+gq)*12 + tig];
                ah[mi][1] = Ah[(rb+gq+8)*12 + tig];
                ah[mi][2] = Ah[(rb+gq)*12 + 4 + tig];
                ah[mi][3] = Ah[(rb+gq+8)*12 + 4 + tig];
                al[mi][0] = Al[(rb+gq)*12 + tig];
                al[mi][1] = Al[(rb+gq+8)*12 + tig];
                al[mi][2] = Al[(rb+gq)*12 + 4 + tig];
                al[mi][3] = Al[(rb+gq+8)*12 + 4 + tig];
            }
            #pragma unroll
            for (int ni = 0; ni < 5; ni++) {
                int cb = wn*40 + ni*8;
                bh[ni][0] = Bh[(cb+gq)*12 + tig];
                bh[ni][1] = Bh[(cb+gq)*12 + 4 + tig];
                bl[ni][0] = Bl[(cb+gq)*12 + tig];
                bl[ni][1] = Bl[(cb+gq)*12 + 4 + tig];
            }
            #pragma unroll
            for (int mi = 0; mi < 2; mi++)
                #pragma unroll
                for (int ni = 0; ni < 5; ni++) {
                    mma_bf16(acc[mi][ni], ah[mi], bh[ni]);
                    mma_bf16(acc[mi][ni], al[mi], bh[ni]);
                    mma_bf16(acc[mi][ni], ah[mi], bl[ni]);
                }
            __syncthreads();
        }
    }
    float* P = g_part + (size_t)ks*MR*GG;
    #pragma unroll
    for (int mi = 0; mi < 2; mi++)
        #pragma unroll
        for (int ni = 0; ni < 5; ni++) {
            int m = m0 + wm*32 + mi*16;
            int n = wn*40 + ni*8 + 2*tig;
            *(float2*)&P[(m+gq)*GG + n]   = make_float2(acc[mi][ni][0], acc[mi][ni][1]);
            *(float2*)&P[(m+gq+8)*GG + n] = make_float2(acc[mi][ni][2], acc[mi][ni][3]);
        }
}

__global__ void reduce_kernel() {
    int idx = blockIdx.x*256 + threadIdx.x;
    if (idx >= MR*GG) return;
    float s = g_pb[idx % GG];
    #pragma unroll
    for (int ks = 0; ks < KSPL; ks++) s += g_part[(size_t)ks*MR*GG + idx];
    g_xproj[idx] = s;
}

// warp-aligned pipelined 2-layer LSTM: warps 0-2 do L0 step t, warps 3-5 do L1 step t-1
__global__ void lstm2_kernel(const float* __restrict__ whh0,
                             const float* __restrict__ wih1, const float* __restrict__ whh1,
                             const float* __restrict__ bih1, const float* __restrict__ bhh1) {
    int b = blockIdx.x, tid = threadIdx.x;   // 192 threads
    __shared__ float h0[20], h1[20], gs0[80], gs1[80];
    float wa[20], wb[20];
    float bias1 = 0.f;
    if (tid < 80) {
        #pragma unroll
        for (int jj = 0; jj < 20; jj++) wa[jj] = whh0[tid*20 + jj];
    } else if (tid >= 96 && tid < 176) {
        int g = tid - 96;
        #pragma unroll
        for (int jj = 0; jj < 20; jj++) {
            wa[jj] = wih1[g*20 + jj];
            wb[jj] = whh1[g*20 + jj];
        }
        bias1 = bih1[g] + bhh1[g];
    }
    float cj = 0.f;
    if (tid < 20) { h0[tid] = 0.f; h1[tid] = 0.f; }
    float xg = (tid < 80) ? g_xproj[(b*LL)*GG + tid] : 0.f;
    __syncthreads();
    for (int t = 0; t <= LL; t++) {
        if (tid < 96) {
            if (tid < 80 && t < LL) {
                float g = xg;
                float a0 = 0.f, a1 = 0.f, a2 = 0.f, a3 = 0.f;
                #pragma unroll
                for (int jj = 0; jj < 20; jj += 4) {
                    a0 = fmaf(wa[jj+0], h0[jj+0], a0);
                    a1 = fmaf(wa[jj+1], h0[jj+1], a1);
                    a2 = fmaf(wa[jj+2], h0[jj+2], a2);
                    a3 = fmaf(wa[jj+3], h0[jj+3], a3);
                }
                g += (a0 + a1) + (a2 + a3);
                gs0[tid] = (tid >= 40 && tid < 60) ? tanh_ap(g) : sigf(g);
                if (t+1 < LL) xg = g_xproj[(b*LL + t+1)*GG + tid];
            }
        } else {
            if (tid < 176 && t >= 1) {
                int gg = tid - 96;
                float g = bias1;
                float a0 = 0.f, a1 = 0.f, a2 = 0.f, a3 = 0.f;
                #pragma unroll
                for (int jj = 0; jj < 20; jj += 4) {
                    a0 = fmaf(wa[jj+0], h0[jj+0], a0);
                    a1 = fmaf(wa[jj+1], h0[jj+1], a1);
                    a2 = fmaf(wa[jj+2], h0[jj+2], a2);
                    a3 = fmaf(wa[jj+3], h0[jj+3], a3);
                }
                #pragma unroll
                for (int jj = 0; jj < 20; jj += 4) {
                    a0 = fmaf(wb[jj+0], h1[jj+0], a0);
                    a1 = fmaf(wb[jj+1], h1[jj+1], a1);
                    a2 = fmaf(wb[jj+2], h1[jj+2], a2);
                    a3 = fmaf(wb[jj+3], h1[jj+3], a3);
                }
                g += (a0 + a1) + (a2 + a3);
                gs1[gg] = (gg >= 40 && gg < 60) ? tanh_ap(g) : sigf(g);
            }
        }
        __syncthreads();
        if (tid < 96) {
            if (tid < 20 && t < LL) {
                cj = fmaf(gs0[20+tid], cj, gs0[tid]*gs0[40+tid]);
                h0[tid] = gs0[60+tid] * tanh_ap(cj);
            }
        } else {
            if (tid < 116 && t >= 1) {
                int j = tid - 96;
                cj = fmaf(gs1[20+j], cj, gs1[j]*gs1[40+j]);
                float hj = gs1[60+j] * tanh_ap(cj);
                h1[j] = hj;
                g_o[(b*LL + (t-1))*HH + j] = hj;
            }
        }
        __syncthreads();
    }
}

__global__ void final_kernel(const float* __restrict__ lw, const float* __restrict__ lb,
                             float* __restrict__ out) {
    int r = blockIdx.x*256 + threadIdx.x;
    if (r >= MR) return;
    float s = lb[0];
    #pragma unroll
    for (int hh = 0; hh < HH; hh++) {
        float v = g_o[r*HH + hh];
        v = (v >= 0.f) ? v : 0.01f*v;
        s = fmaf(v, lw[hh], s);
    }
    out[r] = s;
}

static void run_stage(const float* X, int KP, int KC,
                      const float* wih0, const float* whh0,
                      const float* bih0, const float* bhh0,
                      const float* wih1, const float* whh1,
                      const float* bih1, const float* bhh1,
                      bool first) {
    if (first)
        statsfold_kernel<29, S3OFF1, 32, KP1><<<(KP1 + 127)/128, 256>>>(wih0);
    else
        statsfold_kernel<20, S3OFF2, 20, KP2><<<(KP2 + 127)/128, 256>>>(wih0);
    gemm_tc<<<dim3(MR/128, KSPL), 256>>>(X, KP, KC);
    projbias_kernel<<<GG, 1024>>>(bih0, bhh0, KP);
    reduce_kernel<<<(MR*GG + 255)/256, 256>>>();
    lstm2_kernel<<<BB, 192>>>(whh0, wih1, whh1, bih1, bhh1);
}

extern "C" void kernel_launch(void* const* d_in, const int* in_sizes, int n_in,
                              void* d_out, int out_size) {
    const float* inp = (const float*)d_in[0];
    const float* aw1 = (const float*)d_in[1];
    const float* ab1 = (const float*)d_in[2];
    const float* aw2 = (const float*)d_in[3];
    const float* ab2 = (const float*)d_in[4];
    const float* p[24];
    for (int i = 0; i < 24; i++) p[i] = (const float*)d_in[5 + i];
    const float* lin_w = (const float*)d_in[29];
    const float* lin_b = (const float*)d_in[30];
    float* out = (float*)d_out;

    float* ga;  cudaGetSymbolAddress((void**)&ga,  g_a);
    float* gx1; cudaGetSymbolAddress((void**)&gx1, g_X1);
    float* gx2; cudaGetSymbolAddress((void**)&gx2, g_X2);
    float* go;  cudaGetSymbolAddress((void**)&go,  g_o);

    augment_kernel<<<MR, 64>>>(inp, aw1, ab1, aw2, ab2);
    sig_kernel<29, 32, S3OFF1, KP1, 8><<<dim3(8, BB), 128>>>(ga, 32, gx1);
    run_stage(gx1, KP1, 752, p[0], p[1], p[2], p[3], p[4], p[5], p[6], p[7], true);
    sig_kernel<20, 20, S3OFF2, KP2, 5><<<dim3(5, BB), 96>>>(go, HH, gx2);
    run_stage(gx2, KP2, 240, p[8], p[9], p[10], p[11], p[12], p[13], p[14], p[15], false);
    sig_kernel<20, 20, S3OFF2, KP2, 5><<<dim3(5, BB), 96>>>(go, HH, gx2);
    run_stage(gx2, KP2, 240, p[16], p[17], p[18], p[19], p[20], p[21], p[22], p[23], false);
    final_kernel<<<(MR + 255)/256, 256>>>(lin_w, lin_b, out);
}

// round 14
// speedup vs baseline: 1.7042x; 1.7042x over previous
#include <cuda_runtime.h>
#include <cuda_bf16.h>
#include <math.h>
#include <stdint.h>

#define BB 16
#define LL 128
#define HH 20
#define GG 80
#define MR (BB*LL)
#define KSPL 37
#define KP1 27808
#define S3OFF1 896
#define KP2 8432
#define S3OFF2 432

__device__ __align__(256) float g_a[MR*32];
__device__ __align__(256) float g_X1[(size_t)MR*KP1];
__device__ __align__(256) float g_X2[(size_t)MR*KP2];
__device__ __align__(256) float2 g_sp[(size_t)BB*KP1];
__device__ float g_mean[KP1];
__device__ float g_invstd[KP1];
__device__ __align__(256) unsigned short g_Wh[(size_t)GG*KP1];
__device__ __align__(256) unsigned short g_Wl[(size_t)GG*KP1];
__device__ float g_pb[GG];
__device__ float g_xproj[MR*GG];
__device__ float g_part[(size_t)KSPL*MR*GG];
__device__ float g_o[MR*HH];

__device__ __forceinline__ uint32_t bf2pack(float lo_elem, float hi_elem) {
    uint32_t w;
    asm("cvt.rn.bf16x2.f32 %0, %1, %2;" : "=r"(w) : "f"(hi_elem), "f"(lo_elem));
    return w;
}
__device__ __forceinline__ void split_pair(float vx, float vy, uint32_t& wh, uint32_t& wl) {
    wh = bf2pack(vx, vy);
    float hx = __uint_as_float(wh << 16);
    float hy = __uint_as_float(wh & 0xFFFF0000u);
    wl = bf2pack(vx - hx, vy - hy);
}
__device__ __forceinline__ void mma_bf16(float* c, const uint32_t* a, const uint32_t* b) {
    asm("mma.sync.aligned.m16n8k16.row.col.f32.bf16.bf16.f32 "
        "{%0,%1,%2,%3}, {%4,%5,%6,%7}, {%8,%9}, {%0,%1,%2,%3};"
        : "+f"(c[0]), "+f"(c[1]), "+f"(c[2]), "+f"(c[3])
        : "r"(a[0]), "r"(a[1]), "r"(a[2]), "r"(a[3]), "r"(b[0]), "r"(b[1]));
}
__device__ __forceinline__ float tanh_ap(float x) {
    float y; asm("tanh.approx.f32 %0, %1;" : "=f"(y) : "f"(x)); return y;
}
__device__ __forceinline__ float sigf(float x) { return fmaf(0.5f, tanh_ap(0.5f*x), 0.5f); }

__global__ void augment_kernel(const float* __restrict__ inp,
                               const float* __restrict__ w1, const float* __restrict__ b1,
                               const float* __restrict__ w2, const float* __restrict__ b2) {
    int bl = blockIdx.x;
    int l = bl & (LL-1);
    int tid = threadIdx.x; // 64
    __shared__ float xin[20], hid[64], out8[8];
    if (tid < 20) xin[tid] = inp[bl*20 + tid];
    __syncthreads();
    {
        float a = b1[tid];
        const float* wr = w1 + tid*20;
        #pragma unroll
        for (int c = 0; c < 20; c++) a = fmaf(wr[c], xin[c], a);
        hid[tid] = fmaxf(a, 0.f);
    }
    __syncthreads();
    if (tid < 8) {
        float a = b2[tid];
        const float* wr = w2 + tid*64;
        #pragma unroll 8
        for (int c = 0; c < 64; c++) a = fmaf(wr[c], hid[c], a);
        out8[tid] = a;
    }
    __syncthreads();
    if (tid < 32) {
        float v = 0.f;
        if (tid == 0) v = (float)l * (1.0f/127.0f);
        else if (tid < 21) v = xin[tid-1];
        else if (tid < 29) v = out8[tid-21];
        g_a[bl*32 + tid] = v;
    }
}

// streamed depth-3 signature with fused BN-stat partials
template<int C, int RUN, int S3OFF, int KP, int NSPLIT>
__global__ void sig_kernel(const float* __restrict__ in, int instride,
                           float* __restrict__ X) {
    int g = blockIdx.x, b = blockIdx.y;
    int i0 = (g*C)/NSPLIT, i1 = ((g+1)*C)/NSPLIT;
    int tid = threadIdx.x;
    __shared__ __align__(16) float d[32];
    __shared__ float s1[32];
    int np = (i1 - i0) * C;
    bool act = tid < np;
    int i = i0 + tid / C, j = tid % C;
    int pg = i*C + j;
    float s2r = 0.f, sms2 = 0.f, sqs2 = 0.f;
    float s3r[RUN], sm3[RUN], sq3[RUN];
    #pragma unroll
    for (int q = 0; q < RUN; q++) { s3r[q] = 0.f; sm3[q] = 0.f; sq3[q] = 0.f; }
    float s1sum = 0.f, s1sq = 0.f;
    float prev = 0.f;
    if (tid < 32) { d[tid] = 0.f; s1[tid] = 0.f; }
    float nxt = (tid < C) ? in[(b*LL)*instride + tid] : 0.f;
    __syncthreads();
    for (int t = 0; t < LL; t++) {
        if (tid < 32) {
            float cur = (tid < C) ? nxt : 0.f;
            d[tid] = cur - prev;
            prev = cur;
        }
        __syncthreads();
        if (tid < C && t+1 < LL) nxt = in[(b*LL + t+1)*instride + tid];
        float* Xr = X + (size_t)(b*LL + t)*KP;
        if (act) {
            float di = d[i], dj = d[j], s1i = s1[i];
            float gam = fmaf(dj, fmaf(di, (1.f/6.f), 0.5f*s1i), s2r);
            s2r = fmaf(dj, fmaf(0.5f, di, s1i), s2r);
            sms2 += s2r; sqs2 = fmaf(s2r, s2r, sqs2);
            const float4* d4 = (const float4*)d;
            float4* o4 = (float4*)(Xr + S3OFF + pg*RUN);
            #pragma unroll
            for (int q = 0; q < RUN/4; q++) {
                float4 dq = d4[q];
                s3r[4*q+0] = fmaf(gam, dq.x, s3r[4*q+0]);
                s3r[4*q+1] = fmaf(gam, dq.y, s3r[4*q+1]);
                s3r[4*q+2] = fmaf(gam, dq.z, s3r[4*q+2]);
                s3r[4*q+3] = fmaf(gam, dq.w, s3r[4*q+3]);
                o4[q] = make_float4(s3r[4*q+0], s3r[4*q+1], s3r[4*q+2], s3r[4*q+3]);
                sm3[4*q+0] += s3r[4*q+0]; sq3[4*q+0] = fmaf(s3r[4*q+0], s3r[4*q+0], sq3[4*q+0]);
                sm3[4*q+1] += s3r[4*q+1]; sq3[4*q+1] = fmaf(s3r[4*q+1], s3r[4*q+1], sq3[4*q+1]);
                sm3[4*q+2] += s3r[4*q+2]; sq3[4*q+2] = fmaf(s3r[4*q+2], s3r[4*q+2], sq3[4*q+2]);
                sm3[4*q+3] += s3r[4*q+3]; sq3[4*q+3] = fmaf(s3r[4*q+3], s3r[4*q+3], sq3[4*q+3]);
            }
            Xr[32 + pg] = s2r;
        }
        __syncthreads();
        if (tid < C) s1[tid] += d[tid];
        if (g == 0) {
            float v = 0.f;
            if (tid < C) v = s1[tid];
            if (tid < 32) {
                Xr[tid] = v;
                s1sum += v; s1sq = fmaf(v, v, s1sq);
            }
            int gap0 = 32 + C*C;
            if (gap0 + tid < S3OFF) Xr[gap0 + tid] = 0.f;
        }
    }
    float2* SP = g_sp + (size_t)b*KP;
    if (act) {
        SP[32 + pg] = make_float2(sms2, sqs2);
        #pragma unroll
        for (int q = 0; q < RUN; q++)
            SP[S3OFF + pg*RUN + q] = make_float2(sm3[q], sq3[q]);
    }
    if (g == 0 && tid < 32) {
        SP[tid] = make_float2(s1sum, s1sq);
        int gap0 = 32 + C*C;
        if (gap0 + tid < S3OFF) SP[gap0 + tid] = make_float2(0.f, 0.f);
    }
}

__global__ void finalize_kernel(int KP) {
    int c = blockIdx.x*128 + threadIdx.x;
    if (c >= KP) return;
    double s = 0.0, q = 0.0;
    #pragma unroll
    for (int b = 0; b < BB; b++) {
        float2 v = g_sp[(size_t)b*KP + c];
        s += (double)v.x; q += (double)v.y;
    }
    double m = s * (1.0/2048.0);
    double var = q * (1.0/2048.0) - m*m;
    g_mean[c] = (float)m;
    g_invstd[c] = (float)(1.0 / sqrt(var + 1e-5));
}

template<int C, int S3OFF, int RUN, int KP>
__global__ void wfold_kernel(const float* __restrict__ W) {
    int idx = blockIdx.x*256 + threadIdx.x;
    if (idx >= GG*KP) return;
    int g = idx / KP, cp = idx - g*KP;
    const int CP = C*C;
    int c = -1;
    if (cp < 32) { if (cp < C) c = cp; }
    else if (cp < 32 + CP) c = C + (cp - 32);
    else if (cp >= S3OFF) {
        int r = cp - S3OFF; int p = r / RUN; int k = r - p*RUN;
        if (k < C) c = C + CP + p*C + k;
    }
    float v = 0.f;
    if (c >= 0) v = W[(size_t)g*(C + CP + CP*C) + c] * g_invstd[cp];
    unsigned short hb;
    asm("cvt.rn.bf16.f32 %0, %1;" : "=h"(hb) : "f"(v));
    float hf = __uint_as_float(((uint32_t)hb) << 16);
    unsigned short lb;
    asm("cvt.rn.bf16.f32 %0, %1;" : "=h"(lb) : "f"(v - hf));
    g_Wh[idx] = hb;
    g_Wl[idx] = lb;
}

__global__ void __launch_bounds__(1024) projbias_kernel(const float* __restrict__ bih,
                                                        const float* __restrict__ bhh, int KP) {
    int g = blockIdx.x, tid = threadIdx.x;
    __shared__ double red[1024];
    double s = 0.0;
    for (int c = tid; c < KP; c += 1024) {
        float w = __uint_as_float(((uint32_t)g_Wh[(size_t)g*KP + c]) << 16)
                + __uint_as_float(((uint32_t)g_Wl[(size_t)g*KP + c]) << 16);
        s += (double)w * (double)g_mean[c];
    }
    red[tid] = s; __syncthreads();
    for (int st = 512; st > 0; st >>= 1) { if (tid < st) red[tid] += red[tid+st]; __syncthreads(); }
    if (tid == 0) g_pb[g] = bih[g] + bhh[g] - (float)red[0];
}

// tensor-core GEMM: bf16 2-term split, 3 passes, m16n8k16, double-buffered smem
// (one __syncthreads per k-step), pipelined global loads.
__global__ void __launch_bounds__(256) gemm_tc(const float* __restrict__ X, int KP, int KC) {
    __shared__ __align__(16) uint32_t Ah[2][128*12];
    __shared__ __align__(16) uint32_t Al[2][128*12];
    __shared__ __align__(16) uint32_t Bh[2][80*12];
    __shared__ __align__(16) uint32_t Bl[2][80*12];
    int m0 = blockIdx.x * 128;
    int ks = blockIdx.y;
    int k0 = ks * KC;
    int kend = min(k0 + KC, KP);
    int tid = threadIdx.x;
    int warp = tid >> 5, lane = tid & 31;
    int wm = warp & 3, wn = warp >> 2;
    int gq = lane >> 2, tig = lane & 3;
    float acc[2][5][4];
    #pragma unroll
    for (int mi = 0; mi < 2; mi++)
        #pragma unroll
        for (int ni = 0; ni < 5; ni++)
            #pragma unroll
            for (int q = 0; q < 4; q++) acc[mi][ni][q] = 0.f;

    int arow0 = tid >> 2,        akq0 = (tid & 3) << 2;
    int arow1 = (tid+256) >> 2,  akq1 = akq0;
    int s0 = tid;
    int b0_lo = (s0 >= 160);  int b0r = (b0_lo ? s0-160 : s0) >> 1;  int b0s = s0 & 1;
    int s1v = tid + 256;      bool hasB1 = (s1v < 320);
    int b1r = (s1v-160) >> 1; int b1s = s1v & 1;

    int nsteps = (kend > k0) ? ((kend - k0 + 15) >> 4) : 0;
    if (nsteps > 0) {
        float4 pa0, pa1; uint4 pb0, pb1;
        // preload tile 0
        pa0 = *(const float4*)(X + (size_t)(m0 + arow0)*KP + k0 + akq0);
        pa1 = *(const float4*)(X + (size_t)(m0 + arow1)*KP + k0 + akq1);
        {
            const unsigned short* bp0 = (b0_lo ? g_Wl : g_Wh) + (size_t)b0r*KP + k0 + 8*b0s;
            pb0 = *(const uint4*)bp0;
            if (hasB1) pb1 = *(const uint4*)(g_Wl + (size_t)b1r*KP + k0 + 8*b1s);
        }
        for (int s = 0; s < nsteps; s++) {
            int cur = s & 1;
            // store tile s (regs) into buf[cur]
            {
                uint32_t wh, wl, wh2, wl2;
                split_pair(pa0.x, pa0.y, wh, wl);
                split_pair(pa0.z, pa0.w, wh2, wl2);
                *(uint2*)(Ah[cur] + arow0*12 + (akq0>>1)) = make_uint2(wh, wh2);
                *(uint2*)(Al[cur] + arow0*12 + (akq0>>1)) = make_uint2(wl, wl2);
                split_pair(pa1.x, pa1.y, wh, wl);
                split_pair(pa1.z, pa1.w, wh2, wl2);
                *(uint2*)(Ah[cur] + arow1*12 + (akq1>>1)) = make_uint2(wh, wh2);
                *(uint2*)(Al[cur] + arow1*12 + (akq1>>1)) = make_uint2(wl, wl2);
                uint32_t* bufB = b0_lo ? Bl[cur] : Bh[cur];
                *(uint4*)(bufB + b0r*12 + 4*b0s) = pb0;
                if (hasB1) *(uint4*)(Bl[cur] + b1r*12 + 4*b1s) = pb1;
            }
            // prefetch tile s+1 into regs
            if (s + 1 < nsteps) {
                int kn = k0 + (s+1)*16;
                pa0 = *(const float4*)(X + (size_t)(m0 + arow0)*KP + kn + akq0);
                pa1 = *(const float4*)(X + (size_t)(m0 + arow1)*KP + kn + akq1);
                const unsigned short* bp0 = (b0_lo ? g_Wl : g_Wh) + (size_t)b0r*KP + kn + 8*b0s;
                pb0 = *(const uint4*)bp0;
                if (hasB1) pb1 = *(const uint4*)(g_Wl + (size_t)b1r*KP + kn + 8*b1s);
            }
            __syncthreads();
            // fragments + mma from buf[cur]
            uint32_t ah[2][4], al[2][4], bh[5][2], bl[5][2];
            #pragma unroll
            for (int mi = 0; mi < 2; mi++) {
                int rb = wm*32 + mi*16;
                ah[mi][0] = Ah[cur][(rb+gq)*12 + tig];
                ah[mi][1] = Ah[cur][(rb+gq+8)*12 + tig];
                ah[mi][2] = Ah[cur][(rb+gq)*12 + 4 + tig];
                ah[mi][3] = Ah[cur][(rb+gq+8)*12 + 4 + tig];
                al[mi][0] = Al[cur][(rb+gq)*12 + tig];
                al[mi][1] = Al[cur][(rb+gq+8)*12 + tig];
                al[mi][2] = Al[cur][(rb+gq)*12 + 4 + tig];
                al[mi][3] = Al[cur][(rb+gq+8)*12 + 4 + tig];
            }
            #pragma unroll
            for (int ni = 0; ni < 5; ni++) {
                int cb = wn*40 + ni*8;
                bh[ni][0] = Bh[cur][(cb+gq)*12 + tig];
                bh[ni][1] = Bh[cur][(cb+gq)*12 + 4 + tig];
                bl[ni][0] = Bl[cur][(cb+gq)*12 + tig];
                bl[ni][1] = Bl[cur][(cb+gq)*12 + 4 + tig];
            }
            #pragma unroll
            for (int mi = 0; mi < 2; mi++)
                #pragma unroll
                for (int ni = 0; ni < 5; ni++) {
                    mma_bf16(acc[mi][ni], ah[mi], bh[ni]);
                    mma_bf16(acc[mi][ni], al[mi], bh[ni]);
                    mma_bf16(acc[mi][ni], ah[mi], bl[ni]);
                }
        }
    }
    float* P = g_part + (size_t)ks*MR*GG;
    #pragma unroll
    for (int mi = 0; mi < 2; mi++)
        #pragma unroll
        for (int ni = 0; ni < 5; ni++) {
            int m = m0 + wm*32 + mi*16;
            int n = wn*40 + ni*8 + 2*tig;
            *(float2*)&P[(m+gq)*GG + n]   = make_float2(acc[mi][ni][0], acc[mi][ni][1]);
            *(float2*)&P[(m+gq+8)*GG + n] = make_float2(acc[mi][ni][2], acc[mi][ni][3]);
        }
}

__global__ void reduce_kernel() {
    int idx = blockIdx.x*256 + threadIdx.x;
    if (idx >= MR*GG) return;
    float s = g_pb[idx % GG];
    #pragma unroll
    for (int ks = 0; ks < KSPL; ks++) s += g_part[(size_t)ks*MR*GG + idx];
    g_xproj[idx] = s;
}

// warp-aligned pipelined 2-layer LSTM: warps 0-2 do L0 step t, warps 3-5 do L1 step t-1
__global__ void lstm2_kernel(const float* __restrict__ whh0,
                             const float* __restrict__ wih1, const float* __restrict__ whh1,
                             const float* __restrict__ bih1, const float* __restrict__ bhh1) {
    int b = blockIdx.x, tid = threadIdx.x;   // 192 threads
    __shared__ float h0[20], h1[20], gs0[80], gs1[80];
    float wa[20], wb[20];
    float bias1 = 0.f;
    if (tid < 80) {
        #pragma unroll
        for (int jj = 0; jj < 20; jj++) wa[jj] = whh0[tid*20 + jj];
    } else if (tid >= 96 && tid < 176) {
        int g = tid - 96;
        #pragma unroll
        for (int jj = 0; jj < 20; jj++) {
            wa[jj] = wih1[g*20 + jj];
            wb[jj] = whh1[g*20 + jj];
        }
        bias1 = bih1[g] + bhh1[g];
    }
    float cj = 0.f;
    if (tid < 20) { h0[tid] = 0.f; h1[tid] = 0.f; }
    float xg = (tid < 80) ? g_xproj[(b*LL)*GG + tid] : 0.f;
    __syncthreads();
    for (int t = 0; t <= LL; t++) {
        if (tid < 96) {
            if (tid < 80 && t < LL) {
                float g = xg;
                float a0 = 0.f, a1 = 0.f, a2 = 0.f, a3 = 0.f;
                #pragma unroll
                for (int jj = 0; jj < 20; jj += 4) {
                    a0 = fmaf(wa[jj+0], h0[jj+0], a0);
                    a1 = fmaf(wa[jj+1], h0[jj+1], a1);
                    a2 = fmaf(wa[jj+2], h0[jj+2], a2);
                    a3 = fmaf(wa[jj+3], h0[jj+3], a3);
                }
                g += (a0 + a1) + (a2 + a3);
                gs0[tid] = (tid >= 40 && tid < 60) ? tanh_ap(g) : sigf(g);
                if (t+1 < LL) xg = g_xproj[(b*LL + t+1)*GG + tid];
            }
        } else {
            if (tid < 176 && t >= 1) {
                int gg = tid - 96;
                float g = bias1;
                float a0 = 0.f, a1 = 0.f, a2 = 0.f, a3 = 0.f;
                #pragma unroll
                for (int jj = 0; jj < 20; jj += 4) {
                    a0 = fmaf(wa[jj+0], h0[jj+0], a0);
                    a1 = fmaf(wa[jj+1], h0[jj+1], a1);
                    a2 = fmaf(wa[jj+2], h0[jj+2], a2);
                    a3 = fmaf(wa[jj+3], h0[jj+3], a3);
                }
                #pragma unroll
                for (int jj = 0; jj < 20; jj += 4) {
                    a0 = fmaf(wb[jj+0], h1[jj+0], a0);
                    a1 = fmaf(wb[jj+1], h1[jj+1], a1);
                    a2 = fmaf(wb[jj+2], h1[jj+2], a2);
                    a3 = fmaf(wb[jj+3], h1[jj+3], a3);
                }
                g += (a0 + a1) + (a2 + a3);
                gs1[gg] = (gg >= 40 && gg < 60) ? tanh_ap(g) : sigf(g);
            }
        }
        __syncthreads();
        if (tid < 96) {
            if (tid < 20 && t < LL) {
                cj = fmaf(gs0[20+tid], cj, gs0[tid]*gs0[40+tid]);
                h0[tid] = gs0[60+tid] * tanh_ap(cj);
            }
        } else {
            if (tid < 116 && t >= 1) {
                int j = tid - 96;
                cj = fmaf(gs1[20+j], cj, gs1[j]*gs1[40+j]);
                float hj = gs1[60+j] * tanh_ap(cj);
                h1[j] = hj;
                g_o[(b*LL + (t-1))*HH + j] = hj;
            }
        }
        __syncthreads();
    }
}

__global__ void final_kernel(const float* __restrict__ lw, const float* __restrict__ lb,
                             float* __restrict__ out) {
    int r = blockIdx.x*256 + threadIdx.x;
    if (r >= MR) return;
    float s = lb[0];
    #pragma unroll
    for (int hh = 0; hh < HH; hh++) {
        float v = g_o[r*HH + hh];
        v = (v >= 0.f) ? v : 0.01f*v;
        s = fmaf(v, lw[hh], s);
    }
    out[r] = s;
}

static void run_stage(const float* X, int KP, int KC,
                      const float* wih0, const float* whh0,
                      const float* bih0, const float* bhh0,
                      const float* wih1, const float* whh1,
                      const float* bih1, const float* bhh1,
                      bool first) {
    finalize_kernel<<<(KP + 127)/128, 128>>>(KP);
    if (first)
        wfold_kernel<29, S3OFF1, 32, KP1><<<(GG*KP1 + 255)/256, 256>>>(wih0);
    else
        wfold_kernel<20, S3OFF2, 20, KP2><<<(GG*KP2 + 255)/256, 256>>>(wih0);
    projbias_kernel<<<GG, 1024>>>(bih0, bhh0, KP);
    gemm_tc<<<dim3(MR/128, KSPL), 256>>>(X, KP, KC);
    reduce_kernel<<<(MR*GG + 255)/256, 256>>>();
    lstm2_kernel<<<BB, 192>>>(whh0, wih1, whh1, bih1, bhh1);
}

extern "C" void kernel_launch(void* const* d_in, const int* in_sizes, int n_in,
                              void* d_out, int out_size) {
    const float* inp = (const float*)d_in[0];
    const float* aw1 = (const float*)d_in[1];
    const float* ab1 = (const float*)d_in[2];
    const float* aw2 = (const float*)d_in[3];
    const float* ab2 = (const float*)d_in[4];
    const float* p[24];
    for (int i = 0; i < 24; i++) p[i] = (const float*)d_in[5 + i];
    const float* lin_w = (const float*)d_in[29];
    const float* lin_b = (const float*)d_in[30];
    float* out = (float*)d_out;

    float* ga;  cudaGetSymbolAddress((void**)&ga,  g_a);
    float* gx1; cudaGetSymbolAddress((void**)&gx1, g_X1);
    float* gx2; cudaGetSymbolAddress((void**)&gx2, g_X2);
    float* go;  cudaGetSymbolAddress((void**)&go,  g_o);

    augment_kernel<<<MR, 64>>>(inp, aw1, ab1, aw2, ab2);
    sig_kernel<29, 32, S3OFF1, KP1, 8><<<dim3(8, BB), 128>>>(ga, 32, gx1);
    run_stage(gx1, KP1, 752, p[0], p[1], p[2], p[3], p[4], p[5], p[6], p[7], true);
    sig_kernel<20, 20, S3OFF2, KP2, 5><<<dim3(5, BB), 96>>>(go, HH, gx2);
    run_stage(gx2, KP2, 240, p[8], p[9], p[10], p[11], p[12], p[13], p[14], p[15], false);
    sig_kernel<20, 20, S3OFF2, KP2, 5><<<dim3(5, BB), 96>>>(go, HH, gx2);
    run_stage(gx2, KP2, 240, p[16], p[17], p[18], p[19], p[20], p[21], p[22], p[23], false);
    final_kernel<<<(MR + 255)/256, 256>>>(lin_w, lin_b, out);
}

// round 15
// speedup vs baseline: 1.7456x; 1.0243x over previous
#include <cuda_runtime.h>
#include <cuda_bf16.h>
#include <math.h>
#include <stdint.h>

#define BB 16
#define LL 128
#define HH 20
#define GG 80
#define MR (BB*LL)
#define KSPL 37
#define KP1 27808
#define S3OFF1 896
#define KP2 8432
#define S3OFF2 432

__device__ __align__(256) float g_a[MR*32];
__device__ __align__(256) float g_X1[(size_t)MR*KP1];
__device__ __align__(256) float g_X2[(size_t)MR*KP2];
__device__ __align__(256) float2 g_sp[(size_t)BB*KP1];
__device__ float g_mean[KP1];
__device__ float g_invstd[KP1];
__device__ __align__(256) unsigned short g_Wh[(size_t)GG*KP1];
__device__ __align__(256) unsigned short g_Wl[(size_t)GG*KP1];
__device__ float g_pb[GG];
__device__ float g_xproj[MR*GG];
__device__ float g_part[(size_t)KSPL*MR*GG];
__device__ float g_o[MR*HH];

__device__ __forceinline__ uint32_t bf2pack(float lo_elem, float hi_elem) {
    uint32_t w;
    asm("cvt.rn.bf16x2.f32 %0, %1, %2;" : "=r"(w) : "f"(hi_elem), "f"(lo_elem));
    return w;
}
__device__ __forceinline__ void split_pair(float vx, float vy, uint32_t& wh, uint32_t& wl) {
    wh = bf2pack(vx, vy);
    float hx = __uint_as_float(wh << 16);
    float hy = __uint_as_float(wh & 0xFFFF0000u);
    wl = bf2pack(vx - hx, vy - hy);
}
__device__ __forceinline__ void mma_bf16(float* c, const uint32_t* a, const uint32_t* b) {
    asm("mma.sync.aligned.m16n8k16.row.col.f32.bf16.bf16.f32 "
        "{%0,%1,%2,%3}, {%4,%5,%6,%7}, {%8,%9}, {%0,%1,%2,%3};"
        : "+f"(c[0]), "+f"(c[1]), "+f"(c[2]), "+f"(c[3])
        : "r"(a[0]), "r"(a[1]), "r"(a[2]), "r"(a[3]), "r"(b[0]), "r"(b[1]));
}
__device__ __forceinline__ void ldsm_x4(uint32_t* r, uint32_t addr) {
    asm volatile("ldmatrix.sync.aligned.m8n8.x4.shared.b16 {%0,%1,%2,%3}, [%4];"
        : "=r"(r[0]), "=r"(r[1]), "=r"(r[2]), "=r"(r[3]) : "r"(addr));
}
__device__ __forceinline__ void ldsm_x2(uint32_t* r, uint32_t addr) {
    asm volatile("ldmatrix.sync.aligned.m8n8.x2.shared.b16 {%0,%1}, [%2];"
        : "=r"(r[0]), "=r"(r[1]) : "r"(addr));
}
__device__ __forceinline__ float tanh_ap(float x) {
    float y; asm("tanh.approx.f32 %0, %1;" : "=f"(y) : "f"(x)); return y;
}
__device__ __forceinline__ float sigf(float x) { return fmaf(0.5f, tanh_ap(0.5f*x), 0.5f); }

__global__ void augment_kernel(const float* __restrict__ inp,
                               const float* __restrict__ w1, const float* __restrict__ b1,
                               const float* __restrict__ w2, const float* __restrict__ b2) {
    int bl = blockIdx.x;
    int l = bl & (LL-1);
    int tid = threadIdx.x; // 64
    __shared__ float xin[20], hid[64], out8[8];
    if (tid < 20) xin[tid] = inp[bl*20 + tid];
    __syncthreads();
    {
        float a = b1[tid];
        const float* wr = w1 + tid*20;
        #pragma unroll
        for (int c = 0; c < 20; c++) a = fmaf(wr[c], xin[c], a);
        hid[tid] = fmaxf(a, 0.f);
    }
    __syncthreads();
    if (tid < 8) {
        float a = b2[tid];
        const float* wr = w2 + tid*64;
        #pragma unroll 8
        for (int c = 0; c < 64; c++) a = fmaf(wr[c], hid[c], a);
        out8[tid] = a;
    }
    __syncthreads();
    if (tid < 32) {
        float v = 0.f;
        if (tid == 0) v = (float)l * (1.0f/127.0f);
        else if (tid < 21) v = xin[tid-1];
        else if (tid < 29) v = out8[tid-21];
        g_a[bl*32 + tid] = v;
    }
}

// streamed depth-3 signature with fused BN-stat partials
template<int C, int RUN, int S3OFF, int KP, int NSPLIT>
__global__ void sig_kernel(const float* __restrict__ in, int instride,
                           float* __restrict__ X) {
    int g = blockIdx.x, b = blockIdx.y;
    int i0 = (g*C)/NSPLIT, i1 = ((g+1)*C)/NSPLIT;
    int tid = threadIdx.x;
    __shared__ __align__(16) float d[32];
    __shared__ float s1[32];
    int np = (i1 - i0) * C;
    bool act = tid < np;
    int i = i0 + tid / C, j = tid % C;
    int pg = i*C + j;
    float s2r = 0.f, sms2 = 0.f, sqs2 = 0.f;
    float s3r[RUN], sm3[RUN], sq3[RUN];
    #pragma unroll
    for (int q = 0; q < RUN; q++) { s3r[q] = 0.f; sm3[q] = 0.f; sq3[q] = 0.f; }
    float s1sum = 0.f, s1sq = 0.f;
    float prev = 0.f;
    if (tid < 32) { d[tid] = 0.f; s1[tid] = 0.f; }
    float nxt = (tid < C) ? in[(b*LL)*instride + tid] : 0.f;
    __syncthreads();
    for (int t = 0; t < LL; t++) {
        if (tid < 32) {
            float cur = (tid < C) ? nxt : 0.f;
            d[tid] = cur - prev;
            prev = cur;
        }
        __syncthreads();
        if (tid < C && t+1 < LL) nxt = in[(b*LL + t+1)*instride + tid];
        float* Xr = X + (size_t)(b*LL + t)*KP;
        if (act) {
            float di = d[i], dj = d[j], s1i = s1[i];
            float gam = fmaf(dj, fmaf(di, (1.f/6.f), 0.5f*s1i), s2r);
            s2r = fmaf(dj, fmaf(0.5f, di, s1i), s2r);
            sms2 += s2r; sqs2 = fmaf(s2r, s2r, sqs2);
            const float4* d4 = (const float4*)d;
            float4* o4 = (float4*)(Xr + S3OFF + pg*RUN);
            #pragma unroll
            for (int q = 0; q < RUN/4; q++) {
                float4 dq = d4[q];
                s3r[4*q+0] = fmaf(gam, dq.x, s3r[4*q+0]);
                s3r[4*q+1] = fmaf(gam, dq.y, s3r[4*q+1]);
                s3r[4*q+2] = fmaf(gam, dq.z, s3r[4*q+2]);
                s3r[4*q+3] = fmaf(gam, dq.w, s3r[4*q+3]);
                o4[q] = make_float4(s3r[4*q+0], s3r[4*q+1], s3r[4*q+2], s3r[4*q+3]);
                sm3[4*q+0] += s3r[4*q+0]; sq3[4*q+0] = fmaf(s3r[4*q+0], s3r[4*q+0], sq3[4*q+0]);
                sm3[4*q+1] += s3r[4*q+1]; sq3[4*q+1] = fmaf(s3r[4*q+1], s3r[4*q+1], sq3[4*q+1]);
                sm3[4*q+2] += s3r[4*q+2]; sq3[4*q+2] = fmaf(s3r[4*q+2], s3r[4*q+2], sq3[4*q+2]);
                sm3[4*q+3] += s3r[4*q+3]; sq3[4*q+3] = fmaf(s3r[4*q+3], s3r[4*q+3], sq3[4*q+3]);
            }
            Xr[32 + pg] = s2r;
        }
        __syncthreads();
        if (tid < C) s1[tid] += d[tid];
        if (g == 0) {
            float v = 0.f;
            if (tid < C) v = s1[tid];
            if (tid < 32) {
                Xr[tid] = v;
                s1sum += v; s1sq = fmaf(v, v, s1sq);
            }
            int gap0 = 32 + C*C;
            if (gap0 + tid < S3OFF) Xr[gap0 + tid] = 0.f;
        }
    }
    float2* SP = g_sp + (size_t)b*KP;
    if (act) {
        SP[32 + pg] = make_float2(sms2, sqs2);
        #pragma unroll
        for (int q = 0; q < RUN; q++)
            SP[S3OFF + pg*RUN + q] = make_float2(sm3[q], sq3[q]);
    }
    if (g == 0 && tid < 32) {
        SP[tid] = make_float2(s1sum, s1sq);
        int gap0 = 32 + C*C;
        if (gap0 + tid < S3OFF) SP[gap0 + tid] = make_float2(0.f, 0.f);
    }
}

__global__ void finalize_kernel(int KP) {
    int c = blockIdx.x*128 + threadIdx.x;
    if (c >= KP) return;
    double s = 0.0, q = 0.0;
    #pragma unroll
    for (int b = 0; b < BB; b++) {
        float2 v = g_sp[(size_t)b*KP + c];
        s += (double)v.x; q += (double)v.y;
    }
    double m = s * (1.0/2048.0);
    double var = q * (1.0/2048.0) - m*m;
    g_mean[c] = (float)m;
    g_invstd[c] = (float)(1.0 / sqrt(var + 1e-5));
}

template<int C, int S3OFF, int RUN, int KP>
__global__ void wfold_kernel(const float* __restrict__ W) {
    int idx = blockIdx.x*256 + threadIdx.x;
    if (idx >= GG*KP) return;
    int g = idx / KP, cp = idx - g*KP;
    const int CP = C*C;
    int c = -1;
    if (cp < 32) { if (cp < C) c = cp; }
    else if (cp < 32 + CP) c = C + (cp - 32);
    else if (cp >= S3OFF) {
        int r = cp - S3OFF; int p = r / RUN; int k = r - p*RUN;
        if (k < C) c = C + CP + p*C + k;
    }
    float v = 0.f;
    if (c >= 0) v = W[(size_t)g*(C + CP + CP*C) + c] * g_invstd[cp];
    unsigned short hb;
    asm("cvt.rn.bf16.f32 %0, %1;" : "=h"(hb) : "f"(v));
    float hf = __uint_as_float(((uint32_t)hb) << 16);
    unsigned short lb;
    asm("cvt.rn.bf16.f32 %0, %1;" : "=h"(lb) : "f"(v - hf));
    g_Wh[idx] = hb;
    g_Wl[idx] = lb;
}

__global__ void __launch_bounds__(1024) projbias_kernel(const float* __restrict__ bih,
                                                        const float* __restrict__ bhh, int KP) {
    int g = blockIdx.x, tid = threadIdx.x;
    __shared__ double red[1024];
    double s = 0.0;
    for (int c = tid; c < KP; c += 1024) {
        float w = __uint_as_float(((uint32_t)g_Wh[(size_t)g*KP + c]) << 16)
                + __uint_as_float(((uint32_t)g_Wl[(size_t)g*KP + c]) << 16);
        s += (double)w * (double)g_mean[c];
    }
    red[tid] = s; __syncthreads();
    for (int st = 512; st > 0; st >>= 1) { if (tid < st) red[tid] += red[tid+st]; __syncthreads(); }
    if (tid == 0) g_pb[g] = bih[g] + bhh[g] - (float)red[0];
}

// tensor-core GEMM: bf16 2-term split, 3 passes, m16n8k16, double-buffered smem,
// ldmatrix fragment loads.
__global__ void __launch_bounds__(256) gemm_tc(const float* __restrict__ X, int KP, int KC) {
    __shared__ __align__(16) uint32_t Ah[2][128*12];
    __shared__ __align__(16) uint32_t Al[2][128*12];
    __shared__ __align__(16) uint32_t Bh[2][80*12];
    __shared__ __align__(16) uint32_t Bl[2][80*12];
    int m0 = blockIdx.x * 128;
    int ks = blockIdx.y;
    int k0 = ks * KC;
    int kend = min(k0 + KC, KP);
    int tid = threadIdx.x;
    int warp = tid >> 5, lane = tid & 31;
    int wm = warp & 3, wn = warp >> 2;
    int gq = lane >> 2, tig = lane & 3;
    float acc[2][5][4];
    #pragma unroll
    for (int mi = 0; mi < 2; mi++)
        #pragma unroll
        for (int ni = 0; ni < 5; ni++)
            #pragma unroll
            for (int q = 0; q < 4; q++) acc[mi][ni][q] = 0.f;

    int arow0 = tid >> 2,        akq0 = (tid & 3) << 2;
    int arow1 = (tid+256) >> 2,  akq1 = akq0;
    int s0 = tid;
    int b0_lo = (s0 >= 160);  int b0r = (b0_lo ? s0-160 : s0) >> 1;  int b0s = s0 & 1;
    int s1v = tid + 256;      bool hasB1 = (s1v < 320);
    int b1r = (s1v-160) >> 1; int b1s = s1v & 1;

    // ldmatrix per-lane byte offsets (rows are 12 words = 48 bytes)
    uint32_t aoff  = ((lane < 16) ? (uint32_t)(lane*12) : (uint32_t)((lane-16)*12 + 4)) * 4u;
    uint32_t boff4 = ((lane < 8)  ? (uint32_t)(lane*12)
                     : (lane < 16) ? (uint32_t)((lane-8)*12 + 4)
                     : (lane < 24) ? (uint32_t)((lane-8)*12)
                                   : (uint32_t)((lane-16)*12 + 4)) * 4u;
    uint32_t boff2 = ((lane & 8) ? (uint32_t)((lane & 7)*12 + 4) : (uint32_t)((lane & 7)*12)) * 4u;

    int nsteps = (kend > k0) ? ((kend - k0 + 15) >> 4) : 0;
    if (nsteps > 0) {
        float4 pa0, pa1; uint4 pb0, pb1;
        pa0 = *(const float4*)(X + (size_t)(m0 + arow0)*KP + k0 + akq0);
        pa1 = *(const float4*)(X + (size_t)(m0 + arow1)*KP + k0 + akq1);
        {
            const unsigned short* bp0 = (b0_lo ? g_Wl : g_Wh) + (size_t)b0r*KP + k0 + 8*b0s;
            pb0 = *(const uint4*)bp0;
            if (hasB1) pb1 = *(const uint4*)(g_Wl + (size_t)b1r*KP + k0 + 8*b1s);
        }
        for (int s = 0; s < nsteps; s++) {
            int cur = s & 1;
            {
                uint32_t wh, wl, wh2, wl2;
                split_pair(pa0.x, pa0.y, wh, wl);
                split_pair(pa0.z, pa0.w, wh2, wl2);
                *(uint2*)(Ah[cur] + arow0*12 + (akq0>>1)) = make_uint2(wh, wh2);
                *(uint2*)(Al[cur] + arow0*12 + (akq0>>1)) = make_uint2(wl, wl2);
                split_pair(pa1.x, pa1.y, wh, wl);
                split_pair(pa1.z, pa1.w, wh2, wl2);
                *(uint2*)(Ah[cur] + arow1*12 + (akq1>>1)) = make_uint2(wh, wh2);
                *(uint2*)(Al[cur] + arow1*12 + (akq1>>1)) = make_uint2(wl, wl2);
                uint32_t* bufB = b0_lo ? Bl[cur] : Bh[cur];
                *(uint4*)(bufB + b0r*12 + 4*b0s) = pb0;
                if (hasB1) *(uint4*)(Bl[cur] + b1r*12 + 4*b1s) = pb1;
            }
            if (s + 1 < nsteps) {
                int kn = k0 + (s+1)*16;
                pa0 = *(const float4*)(X + (size_t)(m0 + arow0)*KP + kn + akq0);
                pa1 = *(const float4*)(X + (size_t)(m0 + arow1)*KP + kn + akq1);
                const unsigned short* bp0 = (b0_lo ? g_Wl : g_Wh) + (size_t)b0r*KP + kn + 8*b0s;
                pb0 = *(const uint4*)bp0;
                if (hasB1) pb1 = *(const uint4*)(g_Wl + (size_t)b1r*KP + kn + 8*b1s);
            }
            __syncthreads();
            uint32_t ah[2][4], al[2][4], bh[5][2], bl[5][2];
            uint32_t baseAh = (uint32_t)__cvta_generic_to_shared(Ah[cur]);
            uint32_t baseAl = (uint32_t)__cvta_generic_to_shared(Al[cur]);
            uint32_t baseBh = (uint32_t)__cvta_generic_to_shared(Bh[cur]);
            uint32_t baseBl = (uint32_t)__cvta_generic_to_shared(Bl[cur]);
            #pragma unroll
            for (int mi = 0; mi < 2; mi++) {
                uint32_t rb48 = (uint32_t)(wm*32 + mi*16) * 48u;
                ldsm_x4(ah[mi], baseAh + rb48 + aoff);
                ldsm_x4(al[mi], baseAl + rb48 + aoff);
            }
            {
                uint32_t cb48_0 = (uint32_t)(wn*40) * 48u;
                uint32_t cb48_2 = (uint32_t)(wn*40 + 16) * 48u;
                uint32_t cb48_4 = (uint32_t)(wn*40 + 32) * 48u;
                uint32_t tmp[4];
                ldsm_x4(tmp, baseBh + cb48_0 + boff4);
                bh[0][0]=tmp[0]; bh[0][1]=tmp[1]; bh[1][0]=tmp[2]; bh[1][1]=tmp[3];
                ldsm_x4(tmp, baseBh + cb48_2 + boff4);
                bh[2][0]=tmp[0]; bh[2][1]=tmp[1]; bh[3][0]=tmp[2]; bh[3][1]=tmp[3];
                ldsm_x2(bh[4], baseBh + cb48_4 + boff2);
                ldsm_x4(tmp, baseBl + cb48_0 + boff4);
                bl[0][0]=tmp[0]; bl[0][1]=tmp[1]; bl[1][0]=tmp[2]; bl[1][1]=tmp[3];
                ldsm_x4(tmp, baseBl + cb48_2 + boff4);
                bl[2][0]=tmp[0]; bl[2][1]=tmp[1]; bl[3][0]=tmp[2]; bl[3][1]=tmp[3];
                ldsm_x2(bl[4], baseBl + cb48_4 + boff2);
            }
            #pragma unroll
            for (int mi = 0; mi < 2; mi++)
                #pragma unroll
                for (int ni = 0; ni < 5; ni++) {
                    mma_bf16(acc[mi][ni], ah[mi], bh[ni]);
                    mma_bf16(acc[mi][ni], al[mi], bh[ni]);
                    mma_bf16(acc[mi][ni], ah[mi], bl[ni]);
                }
        }
    }
    float* P = g_part + (size_t)ks*MR*GG;
    #pragma unroll
    for (int mi = 0; mi < 2; mi++)
        #pragma unroll
        for (int ni = 0; ni < 5; ni++) {
            int m = m0 + wm*32 + mi*16;
            int n = wn*40 + ni*8 + 2*tig;
            *(float2*)&P[(m+gq)*GG + n]   = make_float2(acc[mi][ni][0], acc[mi][ni][1]);
            *(float2*)&P[(m+gq+8)*GG + n] = make_float2(acc[mi][ni][2], acc[mi][ni][3]);
        }
}

__global__ void reduce_kernel() {
    int idx = blockIdx.x*256 + threadIdx.x;
    if (idx >= MR*GG) return;
    float s = g_pb[idx % GG];
    #pragma unroll
    for (int ks = 0; ks < KSPL; ks++) s += g_part[(size_t)ks*MR*GG + idx];
    g_xproj[idx] = s;
}

// warp-aligned pipelined 2-layer LSTM
__global__ void lstm2_kernel(const float* __restrict__ whh0,
                             const float* __restrict__ wih1, const float* __restrict__ whh1,
                             const float* __restrict__ bih1, const float* __restrict__ bhh1) {
    int b = blockIdx.x, tid = threadIdx.x;   // 192 threads
    __shared__ float h0[20], h1[20], gs0[80], gs1[80];
    float wa[20], wb[20];
    float bias1 = 0.f;
    if (tid < 80) {
        #pragma unroll
        for (int jj = 0; jj < 20; jj++) wa[jj] = whh0[tid*20 + jj];
    } else if (tid >= 96 && tid < 176) {
        int g = tid - 96;
        #pragma unroll
        for (int jj = 0; jj < 20; jj++) {
            wa[jj] = wih1[g*20 + jj];
            wb[jj] = whh1[g*20 + jj];
        }
        bias1 = bih1[g] + bhh1[g];
    }
    float cj = 0.f;
    if (tid < 20) { h0[tid] = 0.f; h1[tid] = 0.f; }
    float xg = (tid < 80) ? g_xproj[(b*LL)*GG + tid] : 0.f;
    __syncthreads();
    for (int t = 0; t <= LL; t++) {
        if (tid < 96) {
            if (tid < 80 && t < LL) {
                float g = xg;
                float a0 = 0.f, a1 = 0.f, a2 = 0.f, a3 = 0.f;
                #pragma unroll
                for (int jj = 0; jj < 20; jj += 4) {
                    a0 = fmaf(wa[jj+0], h0[jj+0], a0);
                    a1 = fmaf(wa[jj+1], h0[jj+1], a1);
                    a2 = fmaf(wa[jj+2], h0[jj+2], a2);
                    a3 = fmaf(wa[jj+3], h0[jj+3], a3);
                }
                g += (a0 + a1) + (a2 + a3);
                gs0[tid] = (tid >= 40 && tid < 60) ? tanh_ap(g) : sigf(g);
                if (t+1 < LL) xg = g_xproj[(b*LL + t+1)*GG + tid];
            }
        } else {
            if (tid < 176 && t >= 1) {
                int gg = tid - 96;
                float g = bias1;
                float a0 = 0.f, a1 = 0.f, a2 = 0.f, a3 = 0.f;
                #pragma unroll
                for (int jj = 0; jj < 20; jj += 4) {
                    a0 = fmaf(wa[jj+0], h0[jj+0], a0);
                    a1 = fmaf(wa[jj+1], h0[jj+1], a1);
                    a2 = fmaf(wa[jj+2], h0[jj+2], a2);
                    a3 = fmaf(wa[jj+3], h0[jj+3], a3);
                }
                #pragma unroll
                for (int jj = 0; jj < 20; jj += 4) {
                    a0 = fmaf(wb[jj+0], h1[jj+0], a0);
                    a1 = fmaf(wb[jj+1], h1[jj+1], a1);
                    a2 = fmaf(wb[jj+2], h1[jj+2], a2);
                    a3 = fmaf(wb[jj+3], h1[jj+3], a3);
                }
                g += (a0 + a1) + (a2 + a3);
                gs1[gg] = (gg >= 40 && gg < 60) ? tanh_ap(g) : sigf(g);
            }
        }
        __syncthreads();
        if (tid < 96) {
            if (tid < 20 && t < LL) {
                cj = fmaf(gs0[20+tid], cj, gs0[tid]*gs0[40+tid]);
                h0[tid] = gs0[60+tid] * tanh_ap(cj);
            }
        } else {
            if (tid < 116 && t >= 1) {
                int j = tid - 96;
                cj = fmaf(gs1[20+j], cj, gs1[j]*gs1[40+j]);
                float hj = gs1[60+j] * tanh_ap(cj);
                h1[j] = hj;
                g_o[(b*LL + (t-1))*HH + j] = hj;
            }
        }
        __syncthreads();
    }
}

__global__ void final_kernel(const float* __restrict__ lw, const float* __restrict__ lb,
                             float* __restrict__ out) {
    int r = blockIdx.x*256 + threadIdx.x;
    if (r >= MR) return;
    float s = lb[0];
    #pragma unroll
    for (int hh = 0; hh < HH; hh++) {
        float v = g_o[r*HH + hh];
        v = (v >= 0.f) ? v : 0.01f*v;
        s = fmaf(v, lw[hh], s);
    }
    out[r] = s;
}

static void run_stage(const float* X, int KP, int KC,
                      const float* wih0, const float* whh0,
                      const float* bih0, const float* bhh0,
                      const float* wih1, const float* whh1,
                      const float* bih1, const float* bhh1,
                      bool first) {
    finalize_kernel<<<(KP + 127)/128, 128>>>(KP);
    if (first)
        wfold_kernel<29, S3OFF1, 32, KP1><<<(GG*KP1 + 255)/256, 256>>>(wih0);
    else
        wfold_kernel<20, S3OFF2, 20, KP2><<<(GG*KP2 + 255)/256, 256>>>(wih0);
    projbias_kernel<<<GG, 1024>>>(bih0, bhh0, KP);
    gemm_tc<<<dim3(MR/128, KSPL), 256>>>(X, KP, KC);
    reduce_kernel<<<(MR*GG + 255)/256, 256>>>();
    lstm2_kernel<<<BB, 192>>>(whh0, wih1, whh1, bih1, bhh1);
}

extern "C" void kernel_launch(void* const* d_in, const int* in_sizes, int n_in,
                              void* d_out, int out_size) {
    const float* inp = (const float*)d_in[0];
    const float* aw1 = (const float*)d_in[1];
    const float* ab1 = (const float*)d_in[2];
    const float* aw2 = (const float*)d_in[3];
    const float* ab2 = (const float*)d_in[4];
    const float* p[24];
    for (int i = 0; i < 24; i++) p[i] = (const float*)d_in[5 + i];
    const float* lin_w = (const float*)d_in[29];
    const float* lin_b = (const float*)d_in[30];
    float* out = (float*)d_out;

    float* ga;  cudaGetSymbolAddress((void**)&ga,  g_a);
    float* gx1; cudaGetSymbolAddress((void**)&gx1, g_X1);
    float* gx2; cudaGetSymbolAddress((void**)&gx2, g_X2);
    float* go;  cudaGetSymbolAddress((void**)&go,  g_o);

    augment_kernel<<<MR, 64>>>(inp, aw1, ab1, aw2, ab2);
    sig_kernel<29, 32, S3OFF1, KP1, 8><<<dim3(8, BB), 128>>>(ga, 32, gx1);
    run_stage(gx1, KP1, 752, p[0], p[1], p[2], p[3], p[4], p[5], p[6], p[7], true);
    sig_kernel<20, 20, S3OFF2, KP2, 5><<<dim3(5, BB), 96>>>(go, HH, gx2);
    run_stage(gx2, KP2, 240, p[8], p[9], p[10], p[11], p[12], p[13], p[14], p[15], false);
    sig_kernel<20, 20, S3OFF2, KP2, 5><<<dim3(5, BB), 96>>>(go, HH, gx2);
    run_stage(gx2, KP2, 240, p[16], p[17], p[18], p[19], p[20], p[21], p[22], p[23], false);
    final_kernel<<<(MR + 255)/256, 256>>>(lin_w, lin_b, out);
}

// round 16
// speedup vs baseline: 1.7517x; 1.0035x over previous
#include <cuda_runtime.h>
#include <cuda_bf16.h>
#include <math.h>
#include <stdint.h>

#define BB 16
#define LL 128
#define HH 20
#define GG 80
#define MR (BB*LL)
#define KSPL 37
#define KP1 27808
#define S3OFF1 896
#define KP2 8432
#define S3OFF2 432

__device__ __align__(256) float g_a[MR*32];
__device__ __align__(256) float g_X1[(size_t)MR*KP1];
__device__ __align__(256) float g_X2[(size_t)MR*KP2];
__device__ __align__(256) float2 g_sp[(size_t)BB*KP1];
__device__ float g_mean[KP1];
__device__ float g_invstd[KP1];
__device__ __align__(256) unsigned short g_Wh[(size_t)GG*KP1];
__device__ __align__(256) unsigned short g_Wl[(size_t)GG*KP1];
__device__ __align__(16) float g_pb[GG];
__device__ __align__(256) float g_xproj[MR*GG];
__device__ __align__(256) float g_part[(size_t)KSPL*MR*GG];
__device__ __align__(256) float g_o[MR*HH];

__device__ __forceinline__ uint32_t bf2pack(float lo_elem, float hi_elem) {
    uint32_t w;
    asm("cvt.rn.bf16x2.f32 %0, %1, %2;" : "=r"(w) : "f"(hi_elem), "f"(lo_elem));
    return w;
}
__device__ __forceinline__ void split_pair(float vx, float vy, uint32_t& wh, uint32_t& wl) {
    wh = bf2pack(vx, vy);
    float hx = __uint_as_float(wh << 16);
    float hy = __uint_as_float(wh & 0xFFFF0000u);
    wl = bf2pack(vx - hx, vy - hy);
}
__device__ __forceinline__ void mma_bf16(float* c, const uint32_t* a, const uint32_t* b) {
    asm("mma.sync.aligned.m16n8k16.row.col.f32.bf16.bf16.f32 "
        "{%0,%1,%2,%3}, {%4,%5,%6,%7}, {%8,%9}, {%0,%1,%2,%3};"
        : "+f"(c[0]), "+f"(c[1]), "+f"(c[2]), "+f"(c[3])
        : "r"(a[0]), "r"(a[1]), "r"(a[2]), "r"(a[3]), "r"(b[0]), "r"(b[1]));
}
__device__ __forceinline__ void ldsm_x4(uint32_t* r, uint32_t addr) {
    asm volatile("ldmatrix.sync.aligned.m8n8.x4.shared.b16 {%0,%1,%2,%3}, [%4];"
        : "=r"(r[0]), "=r"(r[1]), "=r"(r[2]), "=r"(r[3]) : "r"(addr));
}
__device__ __forceinline__ void ldsm_x2(uint32_t* r, uint32_t addr) {
    asm volatile("ldmatrix.sync.aligned.m8n8.x2.shared.b16 {%0,%1}, [%2];"
        : "=r"(r[0]), "=r"(r[1]) : "r"(addr));
}
__device__ __forceinline__ float tanh_ap(float x) {
    float y; asm("tanh.approx.f32 %0, %1;" : "=f"(y) : "f"(x)); return y;
}
__device__ __forceinline__ float sigf(float x) { return fmaf(0.5f, tanh_ap(0.5f*x), 0.5f); }

__global__ void augment_kernel(const float* __restrict__ inp,
                               const float* __restrict__ w1, const float* __restrict__ b1,
                               const float* __restrict__ w2, const float* __restrict__ b2) {
    int bl = blockIdx.x;
    int l = bl & (LL-1);
    int tid = threadIdx.x; // 64
    __shared__ float xin[20], hid[64], out8[8];
    if (tid < 20) xin[tid] = inp[bl*20 + tid];
    __syncthreads();
    {
        float a = b1[tid];
        const float* wr = w1 + tid*20;
        #pragma unroll
        for (int c = 0; c < 20; c++) a = fmaf(wr[c], xin[c], a);
        hid[tid] = fmaxf(a, 0.f);
    }
    __syncthreads();
    if (tid < 8) {
        float a = b2[tid];
        const float* wr = w2 + tid*64;
        #pragma unroll 8
        for (int c = 0; c < 64; c++) a = fmaf(wr[c], hid[c], a);
        out8[tid] = a;
    }
    __syncthreads();
    if (tid < 32) {
        float v = 0.f;
        if (tid == 0) v = (float)l * (1.0f/127.0f);
        else if (tid < 21) v = xin[tid-1];
        else if (tid < 29) v = out8[tid-21];
        g_a[bl*32 + tid] = v;
    }
}

// streamed depth-3 signature with fused BN-stat partials; double-buffered d/s1,
// single barrier per timestep.
template<int C, int RUN, int S3OFF, int KP, int NSPLIT>
__global__ void sig_kernel(const float* __restrict__ in, int instride,
                           float* __restrict__ X) {
    int g = blockIdx.x, b = blockIdx.y;
    int i0 = (g*C)/NSPLIT, i1 = ((g+1)*C)/NSPLIT;
    int tid = threadIdx.x;
    __shared__ __align__(16) float dbuf[2][32];
    __shared__ float s1buf[2][32];
    int np = (i1 - i0) * C;
    bool act = tid < np;
    int i = i0 + tid / C, j = tid % C;
    int pg = i*C + j;
    float s2r = 0.f, sms2 = 0.f, sqs2 = 0.f;
    float s3r[RUN], sm3[RUN], sq3[RUN];
    #pragma unroll
    for (int q = 0; q < RUN; q++) { s3r[q] = 0.f; sm3[q] = 0.f; sq3[q] = 0.f; }
    float s1sum = 0.f, s1sq = 0.f;
    float prev = 0.f, dreg = 0.f, s1reg = 0.f;
    float nxt = (tid < C) ? in[(b*LL)*instride + tid] : 0.f;
    for (int t = 0; t < LL; t++) {
        int sl = t & 1;
        if (tid < 32) {
            s1reg += dreg;                       // prefix through t-1
            float cur = (tid < C) ? nxt : 0.f;
            dreg = cur - prev;
            prev = cur;
            dbuf[sl][tid] = dreg;
            s1buf[sl][tid] = s1reg;
        }
        __syncthreads();
        if (tid < C && t+1 < LL) nxt = in[(b*LL + t+1)*instride + tid];
        float* Xr = X + (size_t)(b*LL + t)*KP;
        if (act) {
            float di = dbuf[sl][i], dj = dbuf[sl][j], s1i = s1buf[sl][i];
            float gam = fmaf(dj, fmaf(di, (1.f/6.f), 0.5f*s1i), s2r);
            s2r = fmaf(dj, fmaf(0.5f, di, s1i), s2r);
            sms2 += s2r; sqs2 = fmaf(s2r, s2r, sqs2);
            const float4* d4 = (const float4*)dbuf[sl];
            float4* o4 = (float4*)(Xr + S3OFF + pg*RUN);
            #pragma unroll
            for (int q = 0; q < RUN/4; q++) {
                float4 dq = d4[q];
                s3r[4*q+0] = fmaf(gam, dq.x, s3r[4*q+0]);
                s3r[4*q+1] = fmaf(gam, dq.y, s3r[4*q+1]);
                s3r[4*q+2] = fmaf(gam, dq.z, s3r[4*q+2]);
                s3r[4*q+3] = fmaf(gam, dq.w, s3r[4*q+3]);
                o4[q] = make_float4(s3r[4*q+0], s3r[4*q+1], s3r[4*q+2], s3r[4*q+3]);
                sm3[4*q+0] += s3r[4*q+0]; sq3[4*q+0] = fmaf(s3r[4*q+0], s3r[4*q+0], sq3[4*q+0]);
                sm3[4*q+1] += s3r[4*q+1]; sq3[4*q+1] = fmaf(s3r[4*q+1], s3r[4*q+1], sq3[4*q+1]);
                sm3[4*q+2] += s3r[4*q+2]; sq3[4*q+2] = fmaf(s3r[4*q+2], s3r[4*q+2], sq3[4*q+2]);
                sm3[4*q+3] += s3r[4*q+3]; sq3[4*q+3] = fmaf(s3r[4*q+3], s3r[4*q+3], sq3[4*q+3]);
            }
            Xr[32 + pg] = s2r;
        }
        if (g == 0 && tid < 32) {
            float v = (tid < C) ? (s1buf[sl][tid] + dbuf[sl][tid]) : 0.f;   // prefix through t
            Xr[tid] = v;
            s1sum += v; s1sq = fmaf(v, v, s1sq);
            int gap0 = 32 + C*C;
            if (gap0 + tid < S3OFF) Xr[gap0 + tid] = 0.f;
        }
    }
    float2* SP = g_sp + (size_t)b*KP;
    if (act) {
        SP[32 + pg] = make_float2(sms2, sqs2);
        #pragma unroll
        for (int q = 0; q < RUN; q++)
            SP[S3OFF + pg*RUN + q] = make_float2(sm3[q], sq3[q]);
    }
    if (g == 0 && tid < 32) {
        SP[tid] = make_float2(s1sum, s1sq);
        int gap0 = 32 + C*C;
        if (gap0 + tid < S3OFF) SP[gap0 + tid] = make_float2(0.f, 0.f);
    }
}

__global__ void finalize_kernel(int KP) {
    int c = blockIdx.x*128 + threadIdx.x;
    if (c >= KP) return;
    double s = 0.0, q = 0.0;
    #pragma unroll
    for (int b = 0; b < BB; b++) {
        float2 v = g_sp[(size_t)b*KP + c];
        s += (double)v.x; q += (double)v.y;
    }
    double m = s * (1.0/2048.0);
    double var = q * (1.0/2048.0) - m*m;
    g_mean[c] = (float)m;
    g_invstd[c] = (float)(1.0 / sqrt(var + 1e-5));
}

template<int C, int S3OFF, int RUN, int KP>
__global__ void wfold_kernel(const float* __restrict__ W) {
    int idx = blockIdx.x*256 + threadIdx.x;
    if (idx >= GG*KP) return;
    int g = idx / KP, cp = idx - g*KP;
    const int CP = C*C;
    int c = -1;
    if (cp < 32) { if (cp < C) c = cp; }
    else if (cp < 32 + CP) c = C + (cp - 32);
    else if (cp >= S3OFF) {
        int r = cp - S3OFF; int p = r / RUN; int k = r - p*RUN;
        if (k < C) c = C + CP + p*C + k;
    }
    float v = 0.f;
    if (c >= 0) v = W[(size_t)g*(C + CP + CP*C) + c] * g_invstd[cp];
    unsigned short hb;
    asm("cvt.rn.bf16.f32 %0, %1;" : "=h"(hb) : "f"(v));
    float hf = __uint_as_float(((uint32_t)hb) << 16);
    unsigned short lb;
    asm("cvt.rn.bf16.f32 %0, %1;" : "=h"(lb) : "f"(v - hf));
    g_Wh[idx] = hb;
    g_Wl[idx] = lb;
}

__global__ void __launch_bounds__(1024) projbias_kernel(const float* __restrict__ bih,
                                                        const float* __restrict__ bhh, int KP) {
    int g = blockIdx.x, tid = threadIdx.x;
    __shared__ double red[1024];
    double s = 0.0;
    for (int c = tid; c < KP; c += 1024) {
        float w = __uint_as_float(((uint32_t)g_Wh[(size_t)g*KP + c]) << 16)
                + __uint_as_float(((uint32_t)g_Wl[(size_t)g*KP + c]) << 16);
        s += (double)w * (double)g_mean[c];
    }
    red[tid] = s; __syncthreads();
    for (int st = 512; st > 0; st >>= 1) { if (tid < st) red[tid] += red[tid+st]; __syncthreads(); }
    if (tid == 0) g_pb[g] = bih[g] + bhh[g] - (float)red[0];
}

// tensor-core GEMM: bf16 2-term split, 3 passes, m16n8k16, double-buffered smem,
// ldmatrix fragment loads.
__global__ void __launch_bounds__(256) gemm_tc(const float* __restrict__ X, int KP, int KC) {
    __shared__ __align__(16) uint32_t Ah[2][128*12];
    __shared__ __align__(16) uint32_t Al[2][128*12];
    __shared__ __align__(16) uint32_t Bh[2][80*12];
    __shared__ __align__(16) uint32_t Bl[2][80*12];
    int m0 = blockIdx.x * 128;
    int ks = blockIdx.y;
    int k0 = ks * KC;
    int kend = min(k0 + KC, KP);
    int tid = threadIdx.x;
    int warp = tid >> 5, lane = tid & 31;
    int wm = warp & 3, wn = warp >> 2;
    int gq = lane >> 2, tig = lane & 3;
    float acc[2][5][4];
    #pragma unroll
    for (int mi = 0; mi < 2; mi++)
        #pragma unroll
        for (int ni = 0; ni < 5; ni++)
            #pragma unroll
            for (int q = 0; q < 4; q++) acc[mi][ni][q] = 0.f;

    int arow0 = tid >> 2,        akq0 = (tid & 3) << 2;
    int arow1 = (tid+256) >> 2,  akq1 = akq0;
    int s0 = tid;
    int b0_lo = (s0 >= 160);  int b0r = (b0_lo ? s0-160 : s0) >> 1;  int b0s = s0 & 1;
    int s1v = tid + 256;      bool hasB1 = (s1v < 320);
    int b1r = (s1v-160) >> 1; int b1s = s1v & 1;

    uint32_t aoff  = ((lane < 16) ? (uint32_t)(lane*12) : (uint32_t)((lane-16)*12 + 4)) * 4u;
    uint32_t boff4 = ((lane < 8)  ? (uint32_t)(lane*12)
                     : (lane < 16) ? (uint32_t)((lane-8)*12 + 4)
                     : (lane < 24) ? (uint32_t)((lane-8)*12)
                                   : (uint32_t)((lane-16)*12 + 4)) * 4u;
    uint32_t boff2 = ((lane & 8) ? (uint32_t)((lane & 7)*12 + 4) : (uint32_t)((lane & 7)*12)) * 4u;

    int nsteps = (kend > k0) ? ((kend - k0 + 15) >> 4) : 0;
    if (nsteps > 0) {
        float4 pa0, pa1; uint4 pb0, pb1;
        pa0 = *(const float4*)(X + (size_t)(m0 + arow0)*KP + k0 + akq0);
        pa1 = *(const float4*)(X + (size_t)(m0 + arow1)*KP + k0 + akq1);
        {
            const unsigned short* bp0 = (b0_lo ? g_Wl : g_Wh) + (size_t)b0r*KP + k0 + 8*b0s;
            pb0 = *(const uint4*)bp0;
            if (hasB1) pb1 = *(const uint4*)(g_Wl + (size_t)b1r*KP + k0 + 8*b1s);
        }
        for (int s = 0; s < nsteps; s++) {
            int cur = s & 1;
            {
                uint32_t wh, wl, wh2, wl2;
                split_pair(pa0.x, pa0.y, wh, wl);
                split_pair(pa0.z, pa0.w, wh2, wl2);
                *(uint2*)(Ah[cur] + arow0*12 + (akq0>>1)) = make_uint2(wh, wh2);
                *(uint2*)(Al[cur] + arow0*12 + (akq0>>1)) = make_uint2(wl, wl2);
                split_pair(pa1.x, pa1.y, wh, wl);
                split_pair(pa1.z, pa1.w, wh2, wl2);
                *(uint2*)(Ah[cur] + arow1*12 + (akq1>>1)) = make_uint2(wh, wh2);
                *(uint2*)(Al[cur] + arow1*12 + (akq1>>1)) = make_uint2(wl, wl2);
                uint32_t* bufB = b0_lo ? Bl[cur] : Bh[cur];
                *(uint4*)(bufB + b0r*12 + 4*b0s) = pb0;
                if (hasB1) *(uint4*)(Bl[cur] + b1r*12 + 4*b1s) = pb1;
            }
            if (s + 1 < nsteps) {
                int kn = k0 + (s+1)*16;
                pa0 = *(const float4*)(X + (size_t)(m0 + arow0)*KP + kn + akq0);
                pa1 = *(const float4*)(X + (size_t)(m0 + arow1)*KP + kn + akq1);
                const unsigned short* bp0 = (b0_lo ? g_Wl : g_Wh) + (size_t)b0r*KP + kn + 8*b0s;
                pb0 = *(const uint4*)bp0;
                if (hasB1) pb1 = *(const uint4*)(g_Wl + (size_t)b1r*KP + kn + 8*b1s);
            }
            __syncthreads();
            uint32_t ah[2][4], al[2][4], bh[5][2], bl[5][2];
            uint32_t baseAh = (uint32_t)__cvta_generic_to_shared(Ah[cur]);
            uint32_t baseAl = (uint32_t)__cvta_generic_to_shared(Al[cur]);
            uint32_t baseBh = (uint32_t)__cvta_generic_to_shared(Bh[cur]);
            uint32_t baseBl = (uint32_t)__cvta_generic_to_shared(Bl[cur]);
            #pragma unroll
            for (int mi = 0; mi < 2; mi++) {
                uint32_t rb48 = (uint32_t)(wm*32 + mi*16) * 48u;
                ldsm_x4(ah[mi], baseAh + rb48 + aoff);
                ldsm_x4(al[mi], baseAl + rb48 + aoff);
            }
            {
                uint32_t cb48_0 = (uint32_t)(wn*40) * 48u;
                uint32_t cb48_2 = (uint32_t)(wn*40 + 16) * 48u;
                uint32_t cb48_4 = (uint32_t)(wn*40 + 32) * 48u;
                uint32_t tmp[4];
                ldsm_x4(tmp, baseBh + cb48_0 + boff4);
                bh[0][0]=tmp[0]; bh[0][1]=tmp[1]; bh[1][0]=tmp[2]; bh[1][1]=tmp[3];
                ldsm_x4(tmp, baseBh + cb48_2 + boff4);
                bh[2][0]=tmp[0]; bh[2][1]=tmp[1]; bh[3][0]=tmp[2]; bh[3][1]=tmp[3];
                ldsm_x2(bh[4], baseBh + cb48_4 + boff2);
                ldsm_x4(tmp, baseBl + cb48_0 + boff4);
                bl[0][0]=tmp[0]; bl[0][1]=tmp[1]; bl[1][0]=tmp[2]; bl[1][1]=tmp[3];
                ldsm_x4(tmp, baseBl + cb48_2 + boff4);
                bl[2][0]=tmp[0]; bl[2][1]=tmp[1]; bl[3][0]=tmp[2]; bl[3][1]=tmp[3];
                ldsm_x2(bl[4], baseBl + cb48_4 + boff2);
            }
            #pragma unroll
            for (int mi = 0; mi < 2; mi++)
                #pragma unroll
                for (int ni = 0; ni < 5; ni++) {
                    mma_bf16(acc[mi][ni], ah[mi], bh[ni]);
                    mma_bf16(acc[mi][ni], al[mi], bh[ni]);
                    mma_bf16(acc[mi][ni], ah[mi], bl[ni]);
                }
        }
    }
    float* P = g_part + (size_t)ks*MR*GG;
    #pragma unroll
    for (int mi = 0; mi < 2; mi++)
        #pragma unroll
        for (int ni = 0; ni < 5; ni++) {
            int m = m0 + wm*32 + mi*16;
            int n = wn*40 + ni*8 + 2*tig;
            *(float2*)&P[(m+gq)*GG + n]   = make_float2(acc[mi][ni][0], acc[mi][ni][1]);
            *(float2*)&P[(m+gq+8)*GG + n] = make_float2(acc[mi][ni][2], acc[mi][ni][3]);
        }
}

__global__ void reduce_kernel() {
    int idx4 = blockIdx.x*256 + threadIdx.x;
    if (idx4 >= MR*GG/4) return;
    int base = idx4 * 4;
    float4 s = *(const float4*)&g_pb[base % GG];
    #pragma unroll
    for (int ks = 0; ks < KSPL; ks++) {
        float4 p = *(const float4*)&g_part[(size_t)ks*MR*GG + base];
        s.x += p.x; s.y += p.y; s.z += p.z; s.w += p.w;
    }
    *(float4*)&g_xproj[base] = s;
}

// warp-aligned pipelined 2-layer LSTM; optional fused final projection
__global__ void lstm2_kernel(const float* __restrict__ whh0,
                             const float* __restrict__ wih1, const float* __restrict__ whh1,
                             const float* __restrict__ bih1, const float* __restrict__ bhh1,
                             const float* __restrict__ lw, const float* __restrict__ lb,
                             float* __restrict__ out) {
    int b = blockIdx.x, tid = threadIdx.x;   // 192 threads
    __shared__ float h0[20], h1[20], gs0[80], gs1[80];
    float wa[20], wb[20];
    float bias1 = 0.f;
    if (tid < 80) {
        #pragma unroll
        for (int jj = 0; jj < 20; jj++) wa[jj] = whh0[tid*20 + jj];
    } else if (tid >= 96 && tid < 176) {
        int g = tid - 96;
        #pragma unroll
        for (int jj = 0; jj < 20; jj++) {
            wa[jj] = wih1[g*20 + jj];
            wb[jj] = whh1[g*20 + jj];
        }
        bias1 = bih1[g] + bhh1[g];
    }
    float cj = 0.f;
    if (tid < 20) { h0[tid] = 0.f; h1[tid] = 0.f; }
    float xg = (tid < 80) ? g_xproj[(b*LL)*GG + tid] : 0.f;
    __syncthreads();
    for (int t = 0; t <= LL; t++) {
        if (tid < 96) {
            if (tid < 80 && t < LL) {
                float g = xg;
                float a0 = 0.f, a1 = 0.f, a2 = 0.f, a3 = 0.f;
                #pragma unroll
                for (int jj = 0; jj < 20; jj += 4) {
                    a0 = fmaf(wa[jj+0], h0[jj+0], a0);
                    a1 = fmaf(wa[jj+1], h0[jj+1], a1);
                    a2 = fmaf(wa[jj+2], h0[jj+2], a2);
                    a3 = fmaf(wa[jj+3], h0[jj+3], a3);
                }
                g += (a0 + a1) + (a2 + a3);
                gs0[tid] = (tid >= 40 && tid < 60) ? tanh_ap(g) : sigf(g);
                if (t+1 < LL) xg = g_xproj[(b*LL + t+1)*GG + tid];
            }
        } else {
            if (tid < 176 && t >= 1) {
                int gg = tid - 96;
                float g = bias1;
                float a0 = 0.f, a1 = 0.f, a2 = 0.f, a3 = 0.f;
                #pragma unroll
                for (int jj = 0; jj < 20; jj += 4) {
                    a0 = fmaf(wa[jj+0], h0[jj+0], a0);
                    a1 = fmaf(wa[jj+1], h0[jj+1], a1);
                    a2 = fmaf(wa[jj+2], h0[jj+2], a2);
                    a3 = fmaf(wa[jj+3], h0[jj+3], a3);
                }
                #pragma unroll
                for (int jj = 0; jj < 20; jj += 4) {
                    a0 = fmaf(wb[jj+0], h1[jj+0], a0);
                    a1 = fmaf(wb[jj+1], h1[jj+1], a1);
                    a2 = fmaf(wb[jj+2], h1[jj+2], a2);
                    a3 = fmaf(wb[jj+3], h1[jj+3], a3);
                }
                g += (a0 + a1) + (a2 + a3);
                gs1[gg] = (gg >= 40 && gg < 60) ? tanh_ap(g) : sigf(g);
            }
        }
        __syncthreads();
        if (tid < 96) {
            if (tid < 20 && t < LL) {
                cj = fmaf(gs0[20+tid], cj, gs0[tid]*gs0[40+tid]);
                h0[tid] = gs0[60+tid] * tanh_ap(cj);
            }
        } else {
            if (tid < 116 && t >= 1) {
                int j = tid - 96;
                cj = fmaf(gs1[20+j], cj, gs1[j]*gs1[40+j]);
                float hj = gs1[60+j] * tanh_ap(cj);
                h1[j] = hj;
                g_o[(b*LL + (t-1))*HH + j] = hj;
            }
        }
        __syncthreads();
    }
    if (out != nullptr && tid < LL) {
        // fused final: out[b*LL+t] = lb + sum_h leaky(g_o) * lw  (g_o visible after bar)
        int r = b*LL + tid;
        float s = lb[0];
        #pragma unroll
        for (int hh = 0; hh < HH; hh++) {
            float v = g_o[r*HH + hh];
            v = (v >= 0.f) ? v : 0.01f*v;
            s = fmaf(v, lw[hh], s);
        }
        out[r] = s;
    }
}

static void run_stage(const float* X, int KP, int KC,
                      const float* wih0, const float* whh0,
                      const float* bih0, const float* bhh0,
                      const float* wih1, const float* whh1,
                      const float* bih1, const float* bhh1,
                      bool first,
                      const float* lw, const float* lb, float* out) {
    finalize_kernel<<<(KP + 127)/128, 128>>>(KP);
    if (first)
        wfold_kernel<29, S3OFF1, 32, KP1><<<(GG*KP1 + 255)/256, 256>>>(wih0);
    else
        wfold_kernel<20, S3OFF2, 20, KP2><<<(GG*KP2 + 255)/256, 256>>>(wih0);
    projbias_kernel<<<GG, 1024>>>(bih0, bhh0, KP);
    gemm_tc<<<dim3(MR/128, KSPL), 256>>>(X, KP, KC);
    reduce_kernel<<<(MR*GG/4 + 255)/256, 256>>>();
    lstm2_kernel<<<BB, 192>>>(whh0, wih1, whh1, bih1, bhh1, lw, lb, out);
}

extern "C" void kernel_launch(void* const* d_in, const int* in_sizes, int n_in,
                              void* d_out, int out_size) {
    const float* inp = (const float*)d_in[0];
    const float* aw1 = (const float*)d_in[1];
    const float* ab1 = (const float*)d_in[2];
    const float* aw2 = (const float*)d_in[3];
    const float* ab2 = (const float*)d_in[4];
    const float* p[24];
    for (int i = 0; i < 24; i++) p[i] = (const float*)d_in[5 + i];
    const float* lin_w = (const float*)d_in[29];
    const float* lin_b = (const float*)d_in[30];
    float* out = (float*)d_out;

    float* ga;  cudaGetSymbolAddress((void**)&ga,  g_a);
    float* gx1; cudaGetSymbolAddress((void**)&gx1, g_X1);
    float* gx2; cudaGetSymbolAddress((void**)&gx2, g_X2);
    float* go;  cudaGetSymbolAddress((void**)&go,  g_o);

    augment_kernel<<<MR, 64>>>(inp, aw1, ab1, aw2, ab2);
    sig_kernel<29, 32, S3OFF1, KP1, 8><<<dim3(8, BB), 128>>>(ga, 32, gx1);
    run_stage(gx1, KP1, 752, p[0], p[1], p[2], p[3], p[4], p[5], p[6], p[7], true,
              nullptr, nullptr, nullptr);
    sig_kernel<20, 20, S3OFF2, KP2, 5><<<dim3(5, BB), 96>>>(go, HH, gx2);
    run_stage(gx2, KP2, 240, p[8], p[9], p[10], p[11], p[12], p[13], p[14], p[15], false,
              nullptr, nullptr, nullptr);
    sig_kernel<20, 20, S3OFF2, KP2, 5><<<dim3(5, BB), 96>>>(go, HH, gx2);
    run_stage(gx2, KP2, 240, p[16], p[17], p[18], p[19], p[20], p[21], p[22], p[23], false,
              lin_w, lin_b, out);
}

// round 17
// speedup vs baseline: 2.0090x; 1.1468x over previous
#include <cuda_runtime.h>
#include <cuda_bf16.h>
#include <math.h>
#include <stdint.h>

#define BB 16
#define LL 128
#define HH 20
#define GG 80
#define MR (BB*LL)
#define KSPL 37
#define KP1 27808
#define S3OFF1 896
#define KP2 8432
#define S3OFF2 432

__device__ __align__(256) float g_a[MR*32];
__device__ __align__(256) float g_X1[(size_t)MR*KP1];
__device__ __align__(256) float g_X2[(size_t)MR*KP2];
__device__ __align__(256) float2 g_sp[(size_t)BB*KP1];
__device__ __align__(256) float g_mean[KP1];
__device__ float g_invstd[KP1];
__device__ __align__(256) unsigned short g_Wh[(size_t)GG*KP1];
__device__ __align__(256) unsigned short g_Wl[(size_t)GG*KP1];
__device__ __align__(256) float g_xproj[MR*GG];
__device__ __align__(256) float g_part[(size_t)KSPL*MR*GG];
__device__ __align__(256) float g_o[MR*HH];

__device__ __forceinline__ uint32_t bf2pack(float lo_elem, float hi_elem) {
    uint32_t w;
    asm("cvt.rn.bf16x2.f32 %0, %1, %2;" : "=r"(w) : "f"(hi_elem), "f"(lo_elem));
    return w;
}
__device__ __forceinline__ void split_pair(float vx, float vy, uint32_t& wh, uint32_t& wl) {
    wh = bf2pack(vx, vy);
    float hx = __uint_as_float(wh << 16);
    float hy = __uint_as_float(wh & 0xFFFF0000u);
    wl = bf2pack(vx - hx, vy - hy);
}
__device__ __forceinline__ void mma_bf16(float* c, const uint32_t* a, const uint32_t* b) {
    asm("mma.sync.aligned.m16n8k16.row.col.f32.bf16.bf16.f32 "
        "{%0,%1,%2,%3}, {%4,%5,%6,%7}, {%8,%9}, {%0,%1,%2,%3};"
        : "+f"(c[0]), "+f"(c[1]), "+f"(c[2]), "+f"(c[3])
        : "r"(a[0]), "r"(a[1]), "r"(a[2]), "r"(a[3]), "r"(b[0]), "r"(b[1]));
}
__device__ __forceinline__ void ldsm_x4(uint32_t* r, uint32_t addr) {
    asm volatile("ldmatrix.sync.aligned.m8n8.x4.shared.b16 {%0,%1,%2,%3}, [%4];"
        : "=r"(r[0]), "=r"(r[1]), "=r"(r[2]), "=r"(r[3]) : "r"(addr));
}
__device__ __forceinline__ void ldsm_x2(uint32_t* r, uint32_t addr) {
    asm volatile("ldmatrix.sync.aligned.m8n8.x2.shared.b16 {%0,%1}, [%2];"
        : "=r"(r[0]), "=r"(r[1]) : "r"(addr));
}
__device__ __forceinline__ float tanh_ap(float x) {
    float y; asm("tanh.approx.f32 %0, %1;" : "=f"(y) : "f"(x)); return y;
}
__device__ __forceinline__ float sigf(float x) { return fmaf(0.5f, tanh_ap(0.5f*x), 0.5f); }

__global__ void augment_kernel(const float* __restrict__ inp,
                               const float* __restrict__ w1, const float* __restrict__ b1,
                               const float* __restrict__ w2, const float* __restrict__ b2) {
    int bl = blockIdx.x;
    int l = bl & (LL-1);
    int tid = threadIdx.x; // 64
    __shared__ float xin[20], hid[64], out8[8];
    if (tid < 20) xin[tid] = inp[bl*20 + tid];
    __syncthreads();
    {
        float a = b1[tid];
        const float* wr = w1 + tid*20;
        #pragma unroll
        for (int c = 0; c < 20; c++) a = fmaf(wr[c], xin[c], a);
        hid[tid] = fmaxf(a, 0.f);
    }
    __syncthreads();
    if (tid < 8) {
        float a = b2[tid];
        const float* wr = w2 + tid*64;
        #pragma unroll 8
        for (int c = 0; c < 64; c++) a = fmaf(wr[c], hid[c], a);
        out8[tid] = a;
    }
    __syncthreads();
    if (tid < 32) {
        float v = 0.f;
        if (tid == 0) v = (float)l * (1.0f/127.0f);
        else if (tid < 21) v = xin[tid-1];
        else if (tid < 29) v = out8[tid-21];
        g_a[bl*32 + tid] = v;
    }
}

// warp-sized streamed depth-3 signature: one pair-row per CTA (32 threads),
// syncwarp only, shfl for s1/d broadcasts, fused BN-stat partials.
template<int C, int RUN, int S3OFF, int KP>
__global__ void sig_kernel(const float* __restrict__ in, int instride,
                           float* __restrict__ X) {
    int i = blockIdx.x, b = blockIdx.y;
    int tid = threadIdx.x;  // 32
    __shared__ __align__(16) float dsh[32];
    bool act = tid < C;
    int pg = i*C + tid;
    float s2r = 0.f, sms2 = 0.f, sqs2 = 0.f;
    float s3r[RUN], sm3[RUN], sq3[RUN];
    #pragma unroll
    for (int q = 0; q < RUN; q++) { s3r[q] = 0.f; sm3[q] = 0.f; sq3[q] = 0.f; }
    float s1sum = 0.f, s1sq = 0.f;
    float prev = 0.f, dreg = 0.f, s1reg = 0.f;
    float nxt = act ? in[(b*LL)*instride + tid] : 0.f;
    for (int t = 0; t < LL; t++) {
        s1reg += dreg;                 // prefix through t-1
        float cur = act ? nxt : 0.f;
        dreg = cur - prev;
        prev = cur;
        dsh[tid] = dreg;
        __syncwarp();
        if (act && t+1 < LL) nxt = in[(b*LL + t+1)*instride + tid];
        float* Xr = X + (size_t)(b*LL + t)*KP;
        float s1i = __shfl_sync(0xffffffffu, s1reg, i);
        float di  = __shfl_sync(0xffffffffu, dreg,  i);
        if (act) {
            float dj = dreg;
            float gam = fmaf(dj, fmaf(di, (1.f/6.f), 0.5f*s1i), s2r);
            s2r = fmaf(dj, fmaf(0.5f, di, s1i), s2r);
            sms2 += s2r; sqs2 = fmaf(s2r, s2r, sqs2);
            const float4* d4 = (const float4*)dsh;
            float4* o4 = (float4*)(Xr + S3OFF + pg*RUN);
            #pragma unroll
            for (int q = 0; q < RUN/4; q++) {
                float4 dq = d4[q];
                s3r[4*q+0] = fmaf(gam, dq.x, s3r[4*q+0]);
                s3r[4*q+1] = fmaf(gam, dq.y, s3r[4*q+1]);
                s3r[4*q+2] = fmaf(gam, dq.z, s3r[4*q+2]);
                s3r[4*q+3] = fmaf(gam, dq.w, s3r[4*q+3]);
                o4[q] = make_float4(s3r[4*q+0], s3r[4*q+1], s3r[4*q+2], s3r[4*q+3]);
                sm3[4*q+0] += s3r[4*q+0]; sq3[4*q+0] = fmaf(s3r[4*q+0], s3r[4*q+0], sq3[4*q+0]);
                sm3[4*q+1] += s3r[4*q+1]; sq3[4*q+1] = fmaf(s3r[4*q+1], s3r[4*q+1], sq3[4*q+1]);
                sm3[4*q+2] += s3r[4*q+2]; sq3[4*q+2] = fmaf(s3r[4*q+2], s3r[4*q+2], sq3[4*q+2]);
                sm3[4*q+3] += s3r[4*q+3]; sq3[4*q+3] = fmaf(s3r[4*q+3], s3r[4*q+3], sq3[4*q+3]);
            }
            Xr[32 + pg] = s2r;
        }
        if (i == 0) {
            float v = act ? (s1reg + dreg) : 0.f;    // prefix through t
            Xr[tid] = v;
            s1sum += v; s1sq = fmaf(v, v, s1sq);
            int gap0 = 32 + C*C;
            if (gap0 + tid < S3OFF) Xr[gap0 + tid] = 0.f;
        }
        __syncwarp();
    }
    float2* SP = g_sp + (size_t)b*KP;
    if (act) {
        SP[32 + pg] = make_float2(sms2, sqs2);
        #pragma unroll
        for (int q = 0; q < RUN; q++)
            SP[S3OFF + pg*RUN + q] = make_float2(sm3[q], sq3[q]);
    }
    if (i == 0) {
        SP[tid] = make_float2(s1sum, s1sq);
        int gap0 = 32 + C*C;
        if (gap0 + tid < S3OFF) SP[gap0 + tid] = make_float2(0.f, 0.f);
    }
}

__global__ void finalize_kernel(int KP) {
    int c = blockIdx.x*128 + threadIdx.x;
    if (c >= KP) return;
    double s = 0.0, q = 0.0;
    #pragma unroll
    for (int b = 0; b < BB; b++) {
        float2 v = g_sp[(size_t)b*KP + c];
        s += (double)v.x; q += (double)v.y;
    }
    double m = s * (1.0/2048.0);
    double var = q * (1.0/2048.0) - m*m;
    g_mean[c] = (float)m;
    g_invstd[c] = (float)(1.0 / sqrt(var + 1e-5));
}

template<int C, int S3OFF, int RUN, int KP>
__global__ void wfold_kernel(const float* __restrict__ W) {
    int idx = blockIdx.x*256 + threadIdx.x;
    if (idx >= GG*KP) return;
    int g = idx / KP, cp = idx - g*KP;
    const int CP = C*C;
    int c = -1;
    if (cp < 32) { if (cp < C) c = cp; }
    else if (cp < 32 + CP) c = C + (cp - 32);
    else if (cp >= S3OFF) {
        int r = cp - S3OFF; int p = r / RUN; int k = r - p*RUN;
        if (k < C) c = C + CP + p*C + k;
    }
    float v = 0.f;
    if (c >= 0) v = W[(size_t)g*(C + CP + CP*C) + c] * g_invstd[cp];
    unsigned short hb;
    asm("cvt.rn.bf16.f32 %0, %1;" : "=h"(hb) : "f"(v));
    float hf = __uint_as_float(((uint32_t)hb) << 16);
    unsigned short lb;
    asm("cvt.rn.bf16.f32 %0, %1;" : "=h"(lb) : "f"(v - hf));
    g_Wh[idx] = hb;
    g_Wl[idx] = lb;
}

// tensor-core GEMM on mean-centered A: bf16 2-term split, 3 passes, m16n8k16,
// double-buffered smem, ldmatrix fragment loads.
__global__ void __launch_bounds__(256) gemm_tc(const float* __restrict__ X, int KP, int KC) {
    __shared__ __align__(16) uint32_t Ah[2][128*12];
    __shared__ __align__(16) uint32_t Al[2][128*12];
    __shared__ __align__(16) uint32_t Bh[2][80*12];
    __shared__ __align__(16) uint32_t Bl[2][80*12];
    int m0 = blockIdx.x * 128;
    int ks = blockIdx.y;
    int k0 = ks * KC;
    int kend = min(k0 + KC, KP);
    int tid = threadIdx.x;
    int warp = tid >> 5, lane = tid & 31;
    int wm = warp & 3, wn = warp >> 2;
    int gq = lane >> 2, tig = lane & 3;
    float acc[2][5][4];
    #pragma unroll
    for (int mi = 0; mi < 2; mi++)
        #pragma unroll
        for (int ni = 0; ni < 5; ni++)
            #pragma unroll
            for (int q = 0; q < 4; q++) acc[mi][ni][q] = 0.f;

    int arow0 = tid >> 2,        akq0 = (tid & 3) << 2;
    int arow1 = (tid+256) >> 2,  akq1 = akq0;
    int s0 = tid;
    int b0_lo = (s0 >= 160);  int b0r = (b0_lo ? s0-160 : s0) >> 1;  int b0s = s0 & 1;
    int s1v = tid + 256;      bool hasB1 = (s1v < 320);
    int b1r = (s1v-160) >> 1; int b1s = s1v & 1;

    uint32_t aoff  = ((lane < 16) ? (uint32_t)(lane*12) : (uint32_t)((lane-16)*12 + 4)) * 4u;
    uint32_t boff4 = ((lane < 8)  ? (uint32_t)(lane*12)
                     : (lane < 16) ? (uint32_t)((lane-8)*12 + 4)
                     : (lane < 24) ? (uint32_t)((lane-8)*12)
                                   : (uint32_t)((lane-16)*12 + 4)) * 4u;
    uint32_t boff2 = ((lane & 8) ? (uint32_t)((lane & 7)*12 + 4) : (uint32_t)((lane & 7)*12)) * 4u;

    int nsteps = (kend > k0) ? ((kend - k0 + 15) >> 4) : 0;
    if (nsteps > 0) {
        float4 pa0, pa1, pm; uint4 pb0, pb1;
        pa0 = *(const float4*)(X + (size_t)(m0 + arow0)*KP + k0 + akq0);
        pa1 = *(const float4*)(X + (size_t)(m0 + arow1)*KP + k0 + akq1);
        pm  = *(const float4*)(g_mean + k0 + akq0);
        {
            const unsigned short* bp0 = (b0_lo ? g_Wl : g_Wh) + (size_t)b0r*KP + k0 + 8*b0s;
            pb0 = *(const uint4*)bp0;
            if (hasB1) pb1 = *(const uint4*)(g_Wl + (size_t)b1r*KP + k0 + 8*b1s);
        }
        for (int s = 0; s < nsteps; s++) {
            int cur = s & 1;
            {
                uint32_t wh, wl, wh2, wl2;
                split_pair(pa0.x - pm.x, pa0.y - pm.y, wh, wl);
                split_pair(pa0.z - pm.z, pa0.w - pm.w, wh2, wl2);
                *(uint2*)(Ah[cur] + arow0*12 + (akq0>>1)) = make_uint2(wh, wh2);
                *(uint2*)(Al[cur] + arow0*12 + (akq0>>1)) = make_uint2(wl, wl2);
                split_pair(pa1.x - pm.x, pa1.y - pm.y, wh, wl);
                split_pair(pa1.z - pm.z, pa1.w - pm.w, wh2, wl2);
                *(uint2*)(Ah[cur] + arow1*12 + (akq1>>1)) = make_uint2(wh, wh2);
                *(uint2*)(Al[cur] + arow1*12 + (akq1>>1)) = make_uint2(wl, wl2);
                uint32_t* bufB = b0_lo ? Bl[cur] : Bh[cur];
                *(uint4*)(bufB + b0r*12 + 4*b0s) = pb0;
                if (hasB1) *(uint4*)(Bl[cur] + b1r*12 + 4*b1s) = pb1;
            }
            if (s + 1 < nsteps) {
                int kn = k0 + (s+1)*16;
                pa0 = *(const float4*)(X + (size_t)(m0 + arow0)*KP + kn + akq0);
                pa1 = *(const float4*)(X + (size_t)(m0 + arow1)*KP + kn + akq1);
                pm  = *(const float4*)(g_mean + kn + akq0);
                const unsigned short* bp0 = (b0_lo ? g_Wl : g_Wh) + (size_t)b0r*KP + kn + 8*b0s;
                pb0 = *(const uint4*)bp0;
                if (hasB1) pb1 = *(const uint4*)(g_Wl + (size_t)b1r*KP + kn + 8*b1s);
            }
            __syncthreads();
            uint32_t ah[2][4], al[2][4], bh[5][2], bl[5][2];
            uint32_t baseAh = (uint32_t)__cvta_generic_to_shared(Ah[cur]);
            uint32_t baseAl = (uint32_t)__cvta_generic_to_shared(Al[cur]);
            uint32_t baseBh = (uint32_t)__cvta_generic_to_shared(Bh[cur]);
            uint32_t baseBl = (uint32_t)__cvta_generic_to_shared(Bl[cur]);
            #pragma unroll
            for (int mi = 0; mi < 2; mi++) {
                uint32_t rb48 = (uint32_t)(wm*32 + mi*16) * 48u;
                ldsm_x4(ah[mi], baseAh + rb48 + aoff);
                ldsm_x4(al[mi], baseAl + rb48 + aoff);
            }
            {
                uint32_t cb48_0 = (uint32_t)(wn*40) * 48u;
                uint32_t cb48_2 = (uint32_t)(wn*40 + 16) * 48u;
                uint32_t cb48_4 = (uint32_t)(wn*40 + 32) * 48u;
                uint32_t tmp[4];
                ldsm_x4(tmp, baseBh + cb48_0 + boff4);
                bh[0][0]=tmp[0]; bh[0][1]=tmp[1]; bh[1][0]=tmp[2]; bh[1][1]=tmp[3];
                ldsm_x4(tmp, baseBh + cb48_2 + boff4);
                bh[2][0]=tmp[0]; bh[2][1]=tmp[1]; bh[3][0]=tmp[2]; bh[3][1]=tmp[3];
                ldsm_x2(bh[4], baseBh + cb48_4 + boff2);
                ldsm_x4(tmp, baseBl + cb48_0 + boff4);
                bl[0][0]=tmp[0]; bl[0][1]=tmp[1]; bl[1][0]=tmp[2]; bl[1][1]=tmp[3];
                ldsm_x4(tmp, baseBl + cb48_2 + boff4);
                bl[2][0]=tmp[0]; bl[2][1]=tmp[1]; bl[3][0]=tmp[2]; bl[3][1]=tmp[3];
                ldsm_x2(bl[4], baseBl + cb48_4 + boff2);
            }
            #pragma unroll
            for (int mi = 0; mi < 2; mi++)
                #pragma unroll
                for (int ni = 0; ni < 5; ni++) {
                    mma_bf16(acc[mi][ni], ah[mi], bh[ni]);
                    mma_bf16(acc[mi][ni], al[mi], bh[ni]);
                    mma_bf16(acc[mi][ni], ah[mi], bl[ni]);
                }
        }
    }
    float* P = g_part + (size_t)ks*MR*GG;
    #pragma unroll
    for (int mi = 0; mi < 2; mi++)
        #pragma unroll
        for (int ni = 0; ni < 5; ni++) {
            int m = m0 + wm*32 + mi*16;
            int n = wn*40 + ni*8 + 2*tig;
            *(float2*)&P[(m+gq)*GG + n]   = make_float2(acc[mi][ni][0], acc[mi][ni][1]);
            *(float2*)&P[(m+gq+8)*GG + n] = make_float2(acc[mi][ni][2], acc[mi][ni][3]);
        }
}

__global__ void reduce_kernel(const float* __restrict__ bih, const float* __restrict__ bhh) {
    int idx4 = blockIdx.x*256 + threadIdx.x;
    if (idx4 >= MR*GG/4) return;
    int base = idx4 * 4;
    int g = base % GG;
    float4 bi = *(const float4*)&bih[g];
    float4 bh = *(const float4*)&bhh[g];
    float4 s = make_float4(bi.x + bh.x, bi.y + bh.y, bi.z + bh.z, bi.w + bh.w);
    #pragma unroll
    for (int ks = 0; ks < KSPL; ks++) {
        float4 p = *(const float4*)&g_part[(size_t)ks*MR*GG + base];
        s.x += p.x; s.y += p.y; s.z += p.z; s.w += p.w;
    }
    *(float4*)&g_xproj[base] = s;
}

// warp-aligned pipelined 2-layer LSTM; optional fused final projection
__global__ void lstm2_kernel(const float* __restrict__ whh0,
                             const float* __restrict__ wih1, const float* __restrict__ whh1,
                             const float* __restrict__ bih1, const float* __restrict__ bhh1,
                             const float* __restrict__ lw, const float* __restrict__ lb,
                             float* __restrict__ out) {
    int b = blockIdx.x, tid = threadIdx.x;   // 192 threads
    __shared__ float h0[20], h1[20], gs0[80], gs1[80];
    float wa[20], wb[20];
    float bias1 = 0.f;
    if (tid < 80) {
        #pragma unroll
        for (int jj = 0; jj < 20; jj++) wa[jj] = whh0[tid*20 + jj];
    } else if (tid >= 96 && tid < 176) {
        int g = tid - 96;
        #pragma unroll
        for (int jj = 0; jj < 20; jj++) {
            wa[jj] = wih1[g*20 + jj];
            wb[jj] = whh1[g*20 + jj];
        }
        bias1 = bih1[g] + bhh1[g];
    }
    float cj = 0.f;
    if (tid < 20) { h0[tid] = 0.f; h1[tid] = 0.f; }
    float xg = (tid < 80) ? g_xproj[(b*LL)*GG + tid] : 0.f;
    __syncthreads();
    for (int t = 0; t <= LL; t++) {
        if (tid < 96) {
            if (tid < 80 && t < LL) {
                float g = xg;
                float a0 = 0.f, a1 = 0.f, a2 = 0.f, a3 = 0.f;
                #pragma unroll
                for (int jj = 0; jj < 20; jj += 4) {
                    a0 = fmaf(wa[jj+0], h0[jj+0], a0);
                    a1 = fmaf(wa[jj+1], h0[jj+1], a1);
                    a2 = fmaf(wa[jj+2], h0[jj+2], a2);
                    a3 = fmaf(wa[jj+3], h0[jj+3], a3);
                }
                g += (a0 + a1) + (a2 + a3);
                gs0[tid] = (tid >= 40 && tid < 60) ? tanh_ap(g) : sigf(g);
                if (t+1 < LL) xg = g_xproj[(b*LL + t+1)*GG + tid];
            }
        } else {
            if (tid < 176 && t >= 1) {
                int gg = tid - 96;
                float g = bias1;
                float a0 = 0.f, a1 = 0.f, a2 = 0.f, a3 = 0.f;
                #pragma unroll
                for (int jj = 0; jj < 20; jj += 4) {
                    a0 = fmaf(wa[jj+0], h0[jj+0], a0);
                    a1 = fmaf(wa[jj+1], h0[jj+1], a1);
                    a2 = fmaf(wa[jj+2], h0[jj+2], a2);
                    a3 = fmaf(wa[jj+3], h0[jj+3], a3);
                }
                #pragma unroll
                for (int jj = 0; jj < 20; jj += 4) {
                    a0 = fmaf(wb[jj+0], h1[jj+0], a0);
                    a1 = fmaf(wb[jj+1], h1[jj+1], a1);
                    a2 = fmaf(wb[jj+2], h1[jj+2], a2);
                    a3 = fmaf(wb[jj+3], h1[jj+3], a3);
                }
                g += (a0 + a1) + (a2 + a3);
                gs1[gg] = (gg >= 40 && gg < 60) ? tanh_ap(g) : sigf(g);
            }
        }
        __syncthreads();
        if (tid < 96) {
            if (tid < 20 && t < LL) {
                cj = fmaf(gs0[20+tid], cj, gs0[tid]*gs0[40+tid]);
                h0[tid] = gs0[60+tid] * tanh_ap(cj);
            }
        } else {
            if (tid < 116 && t >= 1) {
                int j = tid - 96;
                cj = fmaf(gs1[20+j], cj, gs1[j]*gs1[40+j]);
                float hj = gs1[60+j] * tanh_ap(cj);
                h1[j] = hj;
                g_o[(b*LL + (t-1))*HH + j] = hj;
            }
        }
        __syncthreads();
    }
    if (out != nullptr && tid < LL) {
        int r = b*LL + tid;
        float s = lb[0];
        #pragma unroll
        for (int hh = 0; hh < HH; hh++) {
            float v = g_o[r*HH + hh];
            v = (v >= 0.f) ? v : 0.01f*v;
            s = fmaf(v, lw[hh], s);
        }
        out[r] = s;
    }
}

static void run_stage(const float* X, int KP, int KC,
                      const float* wih0, const float* whh0,
                      const float* bih0, const float* bhh0,
                      const float* wih1, const float* whh1,
                      const float* bih1, const float* bhh1,
                      bool first,
                      const float* lw, const float* lb, float* out) {
    finalize_kernel<<<(KP + 127)/128, 128>>>(KP);
    if (first)
        wfold_kernel<29, S3OFF1, 32, KP1><<<(GG*KP1 + 255)/256, 256>>>(wih0);
    else
        wfold_kernel<20, S3OFF2, 20, KP2><<<(GG*KP2 + 255)/256, 256>>>(wih0);
    gemm_tc<<<dim3(MR/128, KSPL), 256>>>(X, KP, KC);
    reduce_kernel<<<(MR*GG/4 + 255)/256, 256>>>(bih0, bhh0);
    lstm2_kernel<<<BB, 192>>>(whh0, wih1, whh1, bih1, bhh1, lw, lb, out);
}

extern "C" void kernel_launch(void* const* d_in, const int* in_sizes, int n_in,
                              void* d_out, int out_size) {
    const float* inp = (const float*)d_in[0];
    const float* aw1 = (const float*)d_in[1];
    const float* ab1 = (const float*)d_in[2];
    const float* aw2 = (const float*)d_in[3];
    const float* ab2 = (const float*)d_in[4];
    const float* p[24];
    for (int i = 0; i < 24; i++) p[i] = (const float*)d_in[5 + i];
    const float* lin_w = (const float*)d_in[29];
    const float* lin_b = (const float*)d_in[30];
    float* out = (float*)d_out;

    float* ga;  cudaGetSymbolAddress((void**)&ga,  g_a);
    float* gx1; cudaGetSymbolAddress((void**)&gx1, g_X1);
    float* gx2; cudaGetSymbolAddress((void**)&gx2, g_X2);
    float* go;  cudaGetSymbolAddress((void**)&go,  g_o);

    augment_kernel<<<MR, 64>>>(inp, aw1, ab1, aw2, ab2);
    sig_kernel<29, 32, S3OFF1, KP1><<<dim3(29, BB), 32>>>(ga, 32, gx1);
    run_stage(gx1, KP1, 752, p[0], p[1], p[2], p[3], p[4], p[5], p[6], p[7], true,
              nullptr, nullptr, nullptr);
    sig_kernel<20, 20, S3OFF2, KP2><<<dim3(20, BB), 32>>>(go, HH, gx2);
    run_stage(gx2, KP2, 240, p[8], p[9], p[10], p[11], p[12], p[13], p[14], p[15], false,
              nullptr, nullptr, nullptr);
    sig_kernel<20, 20, S3OFF2, KP2><<<dim3(20, BB), 32>>>(go, HH, gx2);
    run_stage(gx2, KP2, 240, p[16], p[17], p[18], p[19], p[20], p[21], p[22], p[23], false,
              lin_w, lin_b, out);
}